// round 5
// baseline (speedup 1.0000x reference)
#include <cuda_runtime.h>
#include <math.h>

// ---- problem constants ----
#define BSZ   32
#define TT    22
#define PP    196
#define DE    2048
#define EE    512
#define HH    512
#define AA    512
#define VV    30000
#define TDEC  20
#define XX    2560   // E + DE
#define G4    2048   // 4*H
#define KAW   2048   // awe part of K in LSTM gemm
#define KS4   2560   // awe + h
#define NBLK  296    // persistent blocks (2 per SM on 148-SM B300; resident on GB300 too)

// ---- output layout ----
#define OFF_PRED  0
#define OFF_ALPHA (BSZ*TDEC*VV)
#define OFF_CAPS  (OFF_ALPHA + BSZ*TDEC*PP)
#define OFF_LEN   (OFF_CAPS + BSZ*TT)
#define OFF_SORT  (OFF_LEN + BSZ)

// ---- device scratch ----
__device__ float g_att1[BSZ*PP*AA];
__device__ float g_hbuf[2*BSZ*HH];
__device__ float g_c[BSZ*HH];
__device__ float g_att2[BSZ*AA];
__device__ float g_gateraw[BSZ*DE];
__device__ float g_escore[BSZ*PP];
__device__ float g_xawe[BSZ*KAW];
__device__ float g_Hall[TDEC*BSZ*HH];
__device__ float g_meanpart[4*BSZ*DE];
__device__ float g_embX[TDEC*BSZ*EE];
__device__ float g_WihET[EE*G4];
__device__ float g_pre[TDEC*BSZ*G4];
__device__ float g_WdaT[AA*HH];
__device__ float g_WfbT[DE*HH];
__device__ float g_Wh0T[HH*DE];
__device__ float g_Wc0T[HH*DE];
__device__ int   g_sortind[BSZ];
__device__ int   g_declen[BSZ];
__device__ int   g_caps[BSZ*TT];
__device__ int   g_rowmapA[BSZ*PP];
__device__ int   g_rowmapC[BSZ*TDEC];
__device__ int   g_activeC[BSZ*TDEC];

// grid barrier state
__device__ unsigned g_bar_count = 0u;
__device__ unsigned g_bar_gen = 0u;

__device__ __forceinline__ float sigm(float x) { return 1.0f / (1.0f + expf(-x)); }

// packed f32x2 helpers (sm_100+)
#define PACKDUP(d, f) asm("mov.b64 %0, {%1, %1};" : "=l"(d) : "r"(__float_as_uint(f)))
#define FMA2(c, a, b) asm("fma.rn.f32x2 %0, %1, %2, %0;" : "+l"(c) : "l"(a), "l"(b))
#define UNPACK2(lo, hi, v) asm("mov.b64 {%0, %1}, %2;" : "=r"(lo), "=r"(hi) : "l"(v))

// software grid barrier (all NBLK blocks resident by construction)
__device__ __forceinline__ void grid_bar() {
    __syncthreads();
    if (threadIdx.x == 0) {
        __threadfence();
        unsigned my = *((volatile unsigned*)&g_bar_gen);
        unsigned old = atomicAdd(&g_bar_count, 1u);
        if (old == NBLK - 1u) {
            atomicExch(&g_bar_count, 0u);
            __threadfence();
            atomicAdd(&g_bar_gen, 1u);
        } else {
            while (*((volatile unsigned*)&g_bar_gen) == my) __nanosleep(32);
            __threadfence();
        }
    }
    __syncthreads();
}

// ============================================================
// Setup
// ============================================================
__global__ void k_setup(const int* __restrict__ captions,
                        const int* __restrict__ cap_len,
                        float* __restrict__ out_caps,
                        float* __restrict__ out_len,
                        float* __restrict__ out_sort) {
    int tid = threadIdx.x;
    __shared__ int s_len[BSZ];
    __shared__ int s_sort[BSZ];
    __shared__ int s_dec[BSZ];
    if (tid < BSZ) s_len[tid] = cap_len[tid];
    __syncthreads();
    if (tid < BSZ) {
        int li = s_len[tid];
        int rank = 0;
        for (int j = 0; j < BSZ; j++) {
            int lj = s_len[j];
            if (lj > li || (lj == li && j < tid)) rank++;
        }
        s_sort[rank] = tid;
    }
    __syncthreads();
    if (tid < BSZ) {
        int src = s_sort[tid];
        g_sortind[tid] = src;
        int L = s_len[src];
        g_declen[tid] = L - 1;
        s_dec[tid]    = L - 1;
        out_len[tid]  = (float)L;
        out_sort[tid] = (float)src;
    }
    __syncthreads();
    for (int i = tid; i < BSZ*TT; i += blockDim.x) {
        int b = i / TT, t = i % TT;
        int v = captions[t*BSZ + s_sort[b]];
        g_caps[i] = v;
        out_caps[i] = (float)v;
    }
    for (int i = tid; i < BSZ*PP; i += blockDim.x) {
        int b = i / PP, p = i % PP;
        g_rowmapA[i] = s_sort[b]*PP + p;
    }
    for (int i = tid; i < BSZ*TDEC; i += blockDim.x) {
        int b = i / TDEC, t = i % TDEC;
        g_rowmapC[i] = t*BSZ + b;
        g_activeC[i] = (t < s_dec[b]) ? 1 : 0;
    }
}

// ============================================================
// Gather embeddings
// ============================================================
__global__ void k_embgather(const float* __restrict__ emb) {
    int t = blockIdx.x, b = blockIdx.y;
    int tok = g_caps[b*TT + t];
    const float* src = emb + (size_t)tok*EE;
    float* dst = g_embX + ((size_t)t*BSZ + b)*EE;
    for (int e = threadIdx.x; e < EE; e += blockDim.x) dst[e] = src[e];
}

// ============================================================
// Transpose
// ============================================================
__global__ void __launch_bounds__(256) k_trans(const float* __restrict__ src, int srcLd,
                                               float* __restrict__ dst, int dstLd) {
    __shared__ float ts[32][33];
    int r0 = blockIdx.x*32, c0 = blockIdx.y*32;
    int tx = threadIdx.x & 31, ty = threadIdx.x >> 5;
    #pragma unroll
    for (int rr = ty; rr < 32; rr += 8)
        ts[rr][tx] = src[(size_t)(r0 + rr)*srcLd + c0 + tx];
    __syncthreads();
    #pragma unroll
    for (int rr = ty; rr < 32; rr += 8)
        dst[(size_t)(c0 + rr)*dstLd + r0 + tx] = ts[tx][rr];
}

// ============================================================
// mean partials
// ============================================================
__global__ void k_meanpart(const float* __restrict__ feat) {
    int b = blockIdx.y, ps = blockIdx.z;
    int d = blockIdx.x*256 + threadIdx.x;
    const float* base = feat + (size_t)g_sortind[b]*PP*DE + d;
    float s = 0.f;
    int p0 = ps*49;
    #pragma unroll 7
    for (int p = p0; p < p0 + 49; p++) s += base[(size_t)p*DE];
    g_meanpart[((ps*BSZ) + b)*DE + d] = s;
}

// ============================================================
// h0/c0 (transposed weights)
// ============================================================
__global__ void __launch_bounds__(256) k_h0c0(const float* __restrict__ bh0,
                                              const float* __restrict__ bc0) {
    __shared__ float xs[BSZ][128];
    int tid = threadIdx.x, lane = tid & 31, w = tid >> 5;
    int c0 = blockIdx.x*8 + (w & 1)*4;
    int b0 = (w >> 1)*8;
    float acc[4][8];
    #pragma unroll
    for (int i = 0; i < 4; i++)
        #pragma unroll
        for (int jx = 0; jx < 8; jx++) acc[i][jx] = 0.f;

    for (int kt = 0; kt < DE/128; kt++) {
        #pragma unroll
        for (int s = 0; s < 16; s++) {
            int idx = tid + s*256;
            int bb = idx >> 7, kk = idx & 127;
            int gd = kt*128 + kk;
            float m = g_meanpart[(0*BSZ + bb)*DE + gd] + g_meanpart[(1*BSZ + bb)*DE + gd]
                    + g_meanpart[(2*BSZ + bb)*DE + gd] + g_meanpart[(3*BSZ + bb)*DE + gd];
            xs[bb][kk] = m * (1.0f/PP);
        }
        __syncthreads();
        #pragma unroll
        for (int kk4 = 0; kk4 < 4; kk4++) {
            int k = kt*128 + kk4*32 + lane;
            float wv[4];
            #pragma unroll
            for (int cc = 0; cc < 4; cc++) {
                int col = c0 + cc;
                wv[cc] = (col < HH) ? g_Wh0T[(size_t)col*DE + k] : g_Wc0T[(size_t)(col - HH)*DE + k];
            }
            #pragma unroll
            for (int cc = 0; cc < 4; cc++)
                #pragma unroll
                for (int bb = 0; bb < 8; bb++)
                    acc[cc][bb] = fmaf(wv[cc], xs[b0+bb][kk4*32+lane], acc[cc][bb]);
        }
        __syncthreads();
    }
    float out = 0.f;
    #pragma unroll
    for (int cc = 0; cc < 4; cc++)
        #pragma unroll
        for (int bb = 0; bb < 8; bb++) {
            float v = acc[cc][bb];
            #pragma unroll
            for (int off = 16; off; off >>= 1) v += __shfl_xor_sync(0xffffffffu, v, off);
            if (lane == cc*8 + bb) out = v;
        }
    int cc = lane >> 3, bb = lane & 7;
    int col = c0 + cc, b = b0 + bb;
    if (col < HH) g_hbuf[b*HH + col]   = out + bh0[col];
    else          g_c[b*HH + col - HH] = out + bc0[col - HH];
}

// ============================================================
// PERSISTENT recurrence kernel: all 20 steps, 4 phases/step,
// software grid barrier between phases.
// ============================================================
__global__ void __launch_bounds__(256, 2) k_loop(
    const float* __restrict__ feat,
    const float* __restrict__ Wfa, const float* __restrict__ bfa,
    const float* __restrict__ bda, const float* __restrict__ bfb,
    const float* __restrict__ Wih, const float* __restrict__ bih,
    const float* __restrict__ Whh, const float* __restrict__ bhh,
    float* __restrict__ out_alphas)
{
    __shared__ __align__(16) float sm[8832];   // 34.5 KB, unioned per phase
    int tid = threadIdx.x, lane = tid & 31, w = tid >> 5;
    int bid = blockIdx.x;

    for (int t = 0; t < TDEC; t++) {
        int cur = t & 1;
        const float* hcur = g_hbuf + cur*BSZ*HH;
        float*       hnxt = g_hbuf + (1 - cur)*BSZ*HH;

        // ================= phase 1: att2/gateraw =================
        {
            float (*xs)[128] = (float(*)[128])sm;
            for (int u = bid; u < XX/8; u += NBLK) {
                int c0 = u*8 + (w & 1)*4;
                int b0 = (w >> 1)*8;
                float acc[4][8];
                #pragma unroll
                for (int i = 0; i < 4; i++)
                    #pragma unroll
                    for (int jx = 0; jx < 8; jx++) acc[i][jx] = 0.f;

                #pragma unroll
                for (int kt = 0; kt < HH/128; kt++) {
                    #pragma unroll
                    for (int s = 0; s < 16; s++) {
                        int idx = tid + s*256;
                        int bb = idx >> 7, kk = idx & 127;
                        xs[bb][kk] = hcur[bb*HH + kt*128 + kk];
                    }
                    __syncthreads();
                    #pragma unroll
                    for (int kk4 = 0; kk4 < 4; kk4++) {
                        int k = kt*128 + kk4*32 + lane;
                        float wv[4];
                        #pragma unroll
                        for (int cc = 0; cc < 4; cc++) {
                            int col = c0 + cc;
                            wv[cc] = (col < AA) ? g_WdaT[(size_t)col*HH + k]
                                                : g_WfbT[(size_t)(col - AA)*HH + k];
                        }
                        #pragma unroll
                        for (int cc = 0; cc < 4; cc++)
                            #pragma unroll
                            for (int bb = 0; bb < 8; bb++)
                                acc[cc][bb] = fmaf(wv[cc], xs[b0+bb][kk4*32+lane], acc[cc][bb]);
                    }
                    __syncthreads();
                }
                float out = 0.f;
                #pragma unroll
                for (int cc = 0; cc < 4; cc++)
                    #pragma unroll
                    for (int bb = 0; bb < 8; bb++) {
                        float v = acc[cc][bb];
                        #pragma unroll
                        for (int off = 16; off; off >>= 1) v += __shfl_xor_sync(0xffffffffu, v, off);
                        if (lane == cc*8 + bb) out = v;
                    }
                int cc = lane >> 3, bb = lane & 7;
                int col = c0 + cc, b = b0 + bb;
                if (col < AA) g_att2[b*AA + col]         = out + bda[col];
                else          g_gateraw[b*DE + col - AA] = out + bfb[col - AA];
            }
        }
        grid_bar();

        // ================= phase 2: attention scores =================
        {
            float4* att2s4 = (float4*)sm;            // 128 float4
            float4* wfas4  = (float4*)(sm + 512);    // 128 float4
            for (int u = bid; u < 800; u += NBLK) {
                int b = u & 31, pg = u >> 5;
                if (tid < 128) {
                    att2s4[tid] = ((const float4*)(g_att2 + b*AA))[tid];
                    wfas4[tid]  = ((const float4*)Wfa)[tid];
                }
                __syncthreads();
                int p = pg*8 + w;
                if (p < PP) {
                    const float4* row4 = (const float4*)(g_att1 + ((size_t)b*PP + p)*AA);
                    float acc = 0.f;
                    #pragma unroll
                    for (int c = 0; c < 4; c++) {
                        int idx = c*32 + lane;
                        float4 v = row4[idx];
                        float4 a2 = att2s4[idx];
                        float4 wf = wfas4[idx];
                        acc = fmaf(fmaxf(v.x + a2.x, 0.f), wf.x, acc);
                        acc = fmaf(fmaxf(v.y + a2.y, 0.f), wf.y, acc);
                        acc = fmaf(fmaxf(v.z + a2.z, 0.f), wf.z, acc);
                        acc = fmaf(fmaxf(v.w + a2.w, 0.f), wf.w, acc);
                    }
                    #pragma unroll
                    for (int off = 16; off; off >>= 1) acc += __shfl_xor_sync(0xffffffffu, acc, off);
                    if (lane == 0) g_escore[b*PP + p] = acc + bfa[0];
                }
                __syncthreads();
            }
        }
        grid_bar();

        // ================= phase 3: softmax + awe + gate =================
        {
            float* als  = sm;          // 196
            float* sred = sm + 256;    // 256
            for (int u = bid; u < 256; u += NBLK) {
                int b = u & 31, chunk = u >> 5;
                float e = (tid < PP) ? g_escore[b*PP + tid] : -3.0e38f;
                sred[tid] = e;
                __syncthreads();
                for (int s = 128; s > 0; s >>= 1) {
                    if (tid < s) sred[tid] = fmaxf(sred[tid], sred[tid+s]);
                    __syncthreads();
                }
                float mx = sred[0];
                __syncthreads();
                float ex = (tid < PP) ? expf(e - mx) : 0.f;
                sred[tid] = ex;
                __syncthreads();
                for (int s = 128; s > 0; s >>= 1) {
                    if (tid < s) sred[tid] += sred[tid+s];
                    __syncthreads();
                }
                float inv = 1.0f / sred[0];
                if (tid < PP) {
                    float al = ex * inv;
                    als[tid] = al;
                    if (chunk == 0) {
                        int active = (t < g_declen[b]);
                        out_alphas[((size_t)b*TDEC + t)*PP + tid] = active ? al : 0.f;
                    }
                }
                __syncthreads();

                int d = chunk*256 + tid;
                const float* base = feat + (size_t)g_sortind[b]*PP*DE + d;
                float s = 0.f;
                #pragma unroll 7
                for (int p = 0; p < PP; p++) s = fmaf(als[p], base[(size_t)p*DE], s);
                float gr = g_gateraw[b*DE + d];
                g_xawe[b*KAW + d] = sigm(gr) * s;
            }
        }
        grid_bar();

        // ================= phase 4: gates GEMM + LSTM cell =================
        {
            float (*xs)[128]      = (float(*)[128])sm;
            float (*red)[BSZ][33] = (float(*)[BSZ][33])(sm + 4096);
            float (*gsum)[BSZ]    = (float(*)[BSZ])(sm + 4096 + 4224);
            for (int u = bid; u < 128; u += NBLK) {
                int jBlock = u*4;
                int r0 = (w >> 1)*4;
                int bh = (w & 1)*16;

                float acc[4][16];
                #pragma unroll
                for (int i = 0; i < 4; i++)
                    #pragma unroll
                    for (int jx = 0; jx < 16; jx++) acc[i][jx] = 0.f;

                const float* wrowIH[4];
                const float* wrowHH[4];
                #pragma unroll
                for (int cc = 0; cc < 4; cc++) {
                    int v = r0 + cc;
                    int wr = (v >> 2)*HH + jBlock + (v & 3);
                    wrowIH[cc] = Wih + (size_t)wr*XX + EE;
                    wrowHH[cc] = Whh + (size_t)wr*HH;
                }

                for (int kt = 0; kt < KS4/128; kt++) {
                    #pragma unroll
                    for (int s = 0; s < 16; s++) {
                        int idx = tid + s*256;
                        int bb = idx >> 7, kk = idx & 127;
                        int gk = kt*128 + kk;
                        xs[bb][kk] = (gk < KAW) ? g_xawe[bb*KAW + gk] : hcur[bb*HH + gk - KAW];
                    }
                    __syncthreads();
                    #pragma unroll
                    for (int kk4 = 0; kk4 < 4; kk4++) {
                        int gk = kt*128 + kk4*32 + lane;
                        float wv[4];
                        #pragma unroll
                        for (int cc = 0; cc < 4; cc++)
                            wv[cc] = (gk < KAW) ? wrowIH[cc][gk] : wrowHH[cc][gk - KAW];
                        #pragma unroll
                        for (int bb = 0; bb < 16; bb++) {
                            float xv = xs[bh + bb][kk4*32 + lane];
                            #pragma unroll
                            for (int cc = 0; cc < 4; cc++)
                                acc[cc][bb] = fmaf(wv[cc], xv, acc[cc][bb]);
                        }
                    }
                    __syncthreads();
                }

                for (int rnd = 0; rnd < 4; rnd++) {
                    if ((w >> 1) == rnd) {
                        #pragma unroll
                        for (int cc = 0; cc < 4; cc++)
                            #pragma unroll
                            for (int bb = 0; bb < 16; bb++)
                                red[cc][bh + bb][lane] = acc[cc][bb];
                    }
                    __syncthreads();
                    if (tid < 128) {
                        int cc = tid >> 5, b = tid & 31;
                        float s = 0.f;
                        #pragma unroll
                        for (int l = 0; l < 32; l++) s += red[cc][b][l];
                        gsum[rnd*4 + cc][b] = s;
                    }
                    __syncthreads();
                }

                if (tid < 128) {
                    int jj = tid >> 5, b = tid & 31;
                    int j = jBlock + jj;
                    size_t pb = ((size_t)t*BSZ + b)*G4;
                    float gi = gsum[0  + jj][b] + bih[0*HH + j] + bhh[0*HH + j] + g_pre[pb + 0*HH + j];
                    float gf = gsum[4  + jj][b] + bih[1*HH + j] + bhh[1*HH + j] + g_pre[pb + 1*HH + j];
                    float gg = gsum[8  + jj][b] + bih[2*HH + j] + bhh[2*HH + j] + g_pre[pb + 2*HH + j];
                    float go = gsum[12 + jj][b] + bih[3*HH + j] + bhh[3*HH + j] + g_pre[pb + 3*HH + j];
                    float c  = g_c[b*HH + j];
                    float cn = sigm(gf)*c + sigm(gi)*tanhf(gg);
                    float hn = sigm(go)*tanhf(cn);
                    int active = (t < g_declen[b]);
                    if (active) g_c[b*HH + j] = cn;
                    hnxt[b*HH + j] = active ? hn : hcur[b*HH + j];
                    g_Hall[((size_t)t*BSZ + b)*HH + j] = hn;
                }
                __syncthreads();
            }
        }
        grid_bar();
    }
}

// ============================================================
// Double-buffered SGEMM with packed f32x2 FMAs (unchanged).
// ============================================================
__global__ void __launch_bounds__(128) k_gemm_db(const float* __restrict__ Aext, int lda_,
                                                 const float* __restrict__ Bext, int ldb_,
                                                 const float* __restrict__ biasext,
                                                 float* __restrict__ Cext, int ldc_,
                                                 int M, int N, int K, int mode) {
    __shared__ __align__(16) float As[2][16][128];
    __shared__ __align__(16) float Bs[2][16][64];
    int tid = threadIdx.x;
    int rowBase = blockIdx.y*128, colBase = blockIdx.x*64;

    const float* Ause; const float* Buse; const float* bias; float* Cuse;
    int lda, ldb, ldc;
    const int* rowmap = nullptr; const int* ract = nullptr;
    if (mode == 0) { Ause = g_embX; lda = EE;  Buse = g_WihET; ldb = G4; bias = nullptr; Cuse = g_pre;  ldc = G4; }
    else if (mode == 1) { Ause = Aext; lda = lda_; Buse = Bext; ldb = ldb_; bias = biasext; Cuse = g_att1; ldc = AA; rowmap = g_rowmapA; }
    else { Ause = g_Hall; lda = HH; Buse = Bext; ldb = ldb_; bias = biasext; Cuse = Cext; ldc = ldc_; rowmap = g_rowmapC; ract = g_activeC; }

    int arow = tid;
    int gRow = rowBase + arow;
    int amap = rowmap ? rowmap[gRow] : gRow;
    const float* aptr = Ause + (size_t)amap*lda;

    int brow = tid >> 4;
    int bcol = (tid & 15)*4;
    int gCol = colBase + bcol;
    bool bval = (gCol < N);

    int tx = tid & 7, ty = tid >> 3;

    unsigned long long accp[4][8];
    #pragma unroll
    for (int q = 0; q < 4; q++)
        #pragma unroll
        for (int jx = 0; jx < 8; jx++) accp[q][jx] = 0ull;

    float4 aR[4], bR[2];
    #pragma unroll
    for (int i = 0; i < 4; i++) aR[i] = *(const float4*)(aptr + i*4);
    #pragma unroll
    for (int i = 0; i < 2; i++)
        bR[i] = bval ? *(const float4*)(Buse + (size_t)(brow + i*8)*ldb + gCol)
                     : make_float4(0.f,0.f,0.f,0.f);
    #pragma unroll
    for (int i = 0; i < 4; i++) {
        As[0][i*4+0][arow] = aR[i].x; As[0][i*4+1][arow] = aR[i].y;
        As[0][i*4+2][arow] = aR[i].z; As[0][i*4+3][arow] = aR[i].w;
    }
    *(float4*)&Bs[0][brow][bcol]   = bR[0];
    *(float4*)&Bs[0][brow+8][bcol] = bR[1];
    __syncthreads();

    int nt = K/16;
    for (int tI = 0; tI < nt; tI++) {
        if (tI + 1 < nt) {
            int k0 = (tI + 1)*16;
            #pragma unroll
            for (int i = 0; i < 4; i++) aR[i] = *(const float4*)(aptr + k0 + i*4);
            #pragma unroll
            for (int i = 0; i < 2; i++)
                bR[i] = bval ? *(const float4*)(Buse + (size_t)(k0 + brow + i*8)*ldb + gCol)
                             : make_float4(0.f,0.f,0.f,0.f);
        }
        int buf = tI & 1;
        #pragma unroll
        for (int k = 0; k < 16; k++) {
            unsigned long long ap[4];
            const unsigned long long* a64 = (const unsigned long long*)&As[buf][k][ty*8];
            ap[0] = a64[0]; ap[1] = a64[1]; ap[2] = a64[2]; ap[3] = a64[3];
            float bfr[8];
            *(float4*)&bfr[0] = *(const float4*)&Bs[buf][k][tx*8];
            *(float4*)&bfr[4] = *(const float4*)&Bs[buf][k][tx*8 + 4];
            unsigned long long b2[8];
            #pragma unroll
            for (int jx = 0; jx < 8; jx++) PACKDUP(b2[jx], bfr[jx]);
            #pragma unroll
            for (int q = 0; q < 4; q++)
                #pragma unroll
                for (int jx = 0; jx < 8; jx++)
                    FMA2(accp[q][jx], ap[q], b2[jx]);
        }
        __syncthreads();
        if (tI + 1 < nt) {
            int nb = buf ^ 1;
            #pragma unroll
            for (int i = 0; i < 4; i++) {
                As[nb][i*4+0][arow] = aR[i].x; As[nb][i*4+1][arow] = aR[i].y;
                As[nb][i*4+2][arow] = aR[i].z; As[nb][i*4+3][arow] = aR[i].w;
            }
            *(float4*)&Bs[nb][brow][bcol]   = bR[0];
            *(float4*)&Bs[nb][brow+8][bcol] = bR[1];
        }
        __syncthreads();
    }

    #pragma unroll
    for (int q = 0; q < 4; q++) {
        int rA = rowBase + ty*8 + 2*q;
        int rB = rA + 1;
        int actA = ract ? ract[rA] : 1;
        int actB = ract ? ract[rB] : 1;
        float* crowA = Cuse + (size_t)rA*ldc;
        float* crowB = Cuse + (size_t)rB*ldc;
        #pragma unroll
        for (int jx = 0; jx < 8; jx++) {
            int c = colBase + tx*8 + jx;
            if (c < N) {
                unsigned lo, hi;
                UNPACK2(lo, hi, accp[q][jx]);
                float bsv = bias ? bias[c] : 0.f;
                crowA[c] = actA ? (__uint_as_float(lo) + bsv) : 0.f;
                crowB[c] = actB ? (__uint_as_float(hi) + bsv) : 0.f;
            }
        }
    }
}

// ============================================================
extern "C" void kernel_launch(void* const* d_in, const int* in_sizes, int n_in,
                              void* d_out, int out_size) {
    const float* feat     = (const float*)d_in[0];
    const int*   captions = (const int*)  d_in[1];
    const int*   caplen   = (const int*)  d_in[2];
    const float* emb      = (const float*)d_in[3];
    const float* Wea = (const float*)d_in[4];  const float* bea = (const float*)d_in[5];
    const float* Wda = (const float*)d_in[6];  const float* bda = (const float*)d_in[7];
    const float* Wfa = (const float*)d_in[8];  const float* bfa = (const float*)d_in[9];
    const float* Wih = (const float*)d_in[10]; const float* bih = (const float*)d_in[11];
    const float* Whh = (const float*)d_in[12]; const float* bhh = (const float*)d_in[13];
    const float* Wh0 = (const float*)d_in[14]; const float* bh0 = (const float*)d_in[15];
    const float* Wc0 = (const float*)d_in[16]; const float* bc0 = (const float*)d_in[17];
    const float* Wfb = (const float*)d_in[18]; const float* bfb = (const float*)d_in[19];
    const float* Wout = (const float*)d_in[20]; const float* bout = (const float*)d_in[21];

    float* out = (float*)d_out;
    float* out_pred  = out + OFF_PRED;
    float* out_alpha = out + OFF_ALPHA;
    float* out_caps  = out + OFF_CAPS;
    float* out_len   = out + OFF_LEN;
    float* out_sort  = out + OFF_SORT;

    float* WihET_dev = nullptr; cudaGetSymbolAddress((void**)&WihET_dev, g_WihET);
    float* WdaT_dev = nullptr;  cudaGetSymbolAddress((void**)&WdaT_dev, g_WdaT);
    float* WfbT_dev = nullptr;  cudaGetSymbolAddress((void**)&WfbT_dev, g_WfbT);
    float* Wh0T_dev = nullptr;  cudaGetSymbolAddress((void**)&Wh0T_dev, g_Wh0T);
    float* Wc0T_dev = nullptr;  cudaGetSymbolAddress((void**)&Wc0T_dev, g_Wc0T);

    // ---- prologue ----
    k_setup<<<1, 256>>>(captions, caplen, out_caps, out_len, out_sort);
    k_embgather<<<dim3(TDEC, BSZ), 128>>>(emb);
    k_trans<<<dim3(2048/32, 512/32), 256>>>(Wih, XX, WihET_dev, G4);
    k_trans<<<dim3(512/32, 512/32),  256>>>(Wda, AA, WdaT_dev, HH);
    k_trans<<<dim3(512/32, 2048/32), 256>>>(Wfb, DE, WfbT_dev, HH);
    k_trans<<<dim3(2048/32, 512/32), 256>>>(Wh0, HH, Wh0T_dev, DE);
    k_trans<<<dim3(2048/32, 512/32), 256>>>(Wc0, HH, Wc0T_dev, DE);
    k_meanpart<<<dim3(DE/256, BSZ, 4), 256>>>(feat);
    k_h0c0<<<128, 256>>>(bh0, bc0);
    // att1 = enc @ Wea + bea : M=6272, N=512, K=2048
    k_gemm_db<<<dim3(AA/64, (BSZ*PP)/128), 128>>>(feat, DE, Wea, AA, bea,
                                                  nullptr, 0, BSZ*PP, AA, DE, 1);
    // pre = embX @ WihET : M=640, N=2048, K=512
    k_gemm_db<<<dim3(G4/64, (TDEC*BSZ)/128), 128>>>(nullptr, 0, nullptr, 0, nullptr,
                                                    nullptr, 0, TDEC*BSZ, G4, EE, 0);

    // ---- recurrence: single persistent kernel ----
    k_loop<<<NBLK, 256>>>(feat, Wfa, bfa, bda, bfb, Wih, bih, Whh, bhh, out_alpha);

    // ---- epilogue: preds = Hall @ Wout + bout : M=640, N=30000, K=512 ----
    k_gemm_db<<<dim3((VV + 63)/64, (TDEC*BSZ)/128), 128>>>(nullptr, 0, Wout, VV, bout,
                                                           out_pred, VV, TDEC*BSZ, VV, HH, 2);
}

// round 6
// speedup vs baseline: 1.3615x; 1.3615x over previous
#include <cuda_runtime.h>
#include <math.h>

// ---- problem constants ----
#define BSZ   32
#define TT    22
#define PP    196
#define DE    2048
#define EE    512
#define HH    512
#define AA    512
#define VV    30000
#define TDEC  20
#define XX    2560   // E + DE
#define G4    2048   // 4*H
#define KAW   2048   // awe part of K in LSTM gemm
#define KS4   2560   // awe + h

// ---- output layout ----
#define OFF_PRED  0
#define OFF_ALPHA (BSZ*TDEC*VV)
#define OFF_CAPS  (OFF_ALPHA + BSZ*TDEC*PP)
#define OFF_LEN   (OFF_CAPS + BSZ*TT)
#define OFF_SORT  (OFF_LEN + BSZ)

// ---- device scratch ----
__device__ float g_att1[BSZ*PP*AA];
__device__ float g_hbuf[2*BSZ*HH];
__device__ float g_c[BSZ*HH];
__device__ float g_att2[BSZ*AA];
__device__ float g_gateraw[BSZ*DE];
__device__ float g_escore[BSZ*PP];
__device__ float g_xawe[BSZ*KAW];
__device__ float g_Hall[TDEC*BSZ*HH];
__device__ float g_meanpart[4*BSZ*DE];
__device__ float g_embX[TDEC*BSZ*EE];
__device__ float g_WihET[EE*G4];
__device__ float g_pre[TDEC*BSZ*G4];
__device__ float g_WdaT[AA*HH];
__device__ float g_WfbT[DE*HH];
__device__ float g_Wh0T[HH*DE];
__device__ float g_Wc0T[HH*DE];
__device__ int   g_sortind[BSZ];
__device__ int   g_declen[BSZ];
__device__ int   g_caps[BSZ*TT];
__device__ int   g_rowmapA[BSZ*PP];
__device__ int   g_rowmapC[BSZ*TDEC];
__device__ int   g_activeC[BSZ*TDEC];

__device__ __forceinline__ float sigm(float x) { return 1.0f / (1.0f + expf(-x)); }

__device__ __forceinline__ unsigned f2tf32(float f) {
    unsigned r;
    asm("cvt.rna.tf32.f32 %0, %1;" : "=r"(r) : "f"(f));
    return r;
}

__device__ __forceinline__ void mma_tf32(float* d, const uint4& a, const uint2& b) {
    asm("mma.sync.aligned.m16n8k8.row.col.f32.tf32.tf32.f32 "
        "{%0,%1,%2,%3},{%4,%5,%6,%7},{%8,%9},{%0,%1,%2,%3};"
        : "+f"(d[0]), "+f"(d[1]), "+f"(d[2]), "+f"(d[3])
        : "r"(a.x), "r"(a.y), "r"(a.z), "r"(a.w), "r"(b.x), "r"(b.y));
}

// ============================================================
// Setup
// ============================================================
__global__ void k_setup(const int* __restrict__ captions,
                        const int* __restrict__ cap_len,
                        float* __restrict__ out_caps,
                        float* __restrict__ out_len,
                        float* __restrict__ out_sort) {
    int tid = threadIdx.x;
    __shared__ int s_len[BSZ];
    __shared__ int s_sort[BSZ];
    __shared__ int s_dec[BSZ];
    if (tid < BSZ) s_len[tid] = cap_len[tid];
    __syncthreads();
    if (tid < BSZ) {
        int li = s_len[tid];
        int rank = 0;
        for (int j = 0; j < BSZ; j++) {
            int lj = s_len[j];
            if (lj > li || (lj == li && j < tid)) rank++;
        }
        s_sort[rank] = tid;
    }
    __syncthreads();
    if (tid < BSZ) {
        int src = s_sort[tid];
        g_sortind[tid] = src;
        int L = s_len[src];
        g_declen[tid] = L - 1;
        s_dec[tid]    = L - 1;
        out_len[tid]  = (float)L;
        out_sort[tid] = (float)src;
    }
    __syncthreads();
    for (int i = tid; i < BSZ*TT; i += blockDim.x) {
        int b = i / TT, t = i % TT;
        int v = captions[t*BSZ + s_sort[b]];
        g_caps[i] = v;
        out_caps[i] = (float)v;
    }
    for (int i = tid; i < BSZ*PP; i += blockDim.x) {
        int b = i / PP, p = i % PP;
        g_rowmapA[i] = s_sort[b]*PP + p;
    }
    for (int i = tid; i < BSZ*TDEC; i += blockDim.x) {
        int b = i / TDEC, t = i % TDEC;
        g_rowmapC[i] = t*BSZ + b;
        g_activeC[i] = (t < s_dec[b]) ? 1 : 0;
    }
}

// ============================================================
// Gather embeddings
// ============================================================
__global__ void k_embgather(const float* __restrict__ emb) {
    int t = blockIdx.x, b = blockIdx.y;
    int tok = g_caps[b*TT + t];
    const float* src = emb + (size_t)tok*EE;
    float* dst = g_embX + ((size_t)t*BSZ + b)*EE;
    for (int e = threadIdx.x; e < EE; e += blockDim.x) dst[e] = src[e];
}

// ============================================================
// Transpose
// ============================================================
__global__ void __launch_bounds__(256) k_trans(const float* __restrict__ src, int srcLd,
                                               float* __restrict__ dst, int dstLd) {
    __shared__ float ts[32][33];
    int r0 = blockIdx.x*32, c0 = blockIdx.y*32;
    int tx = threadIdx.x & 31, ty = threadIdx.x >> 5;
    #pragma unroll
    for (int rr = ty; rr < 32; rr += 8)
        ts[rr][tx] = src[(size_t)(r0 + rr)*srcLd + c0 + tx];
    __syncthreads();
    #pragma unroll
    for (int rr = ty; rr < 32; rr += 8)
        dst[(size_t)(c0 + rr)*dstLd + r0 + tx] = ts[tx][rr];
}

// ============================================================
// mean partials
// ============================================================
__global__ void k_meanpart(const float* __restrict__ feat) {
    int b = blockIdx.y, ps = blockIdx.z;
    int d = blockIdx.x*256 + threadIdx.x;
    const float* base = feat + (size_t)g_sortind[b]*PP*DE + d;
    float s = 0.f;
    int p0 = ps*49;
    #pragma unroll 7
    for (int p = p0; p < p0 + 49; p++) s += base[(size_t)p*DE];
    g_meanpart[((ps*BSZ) + b)*DE + d] = s;
}

// ============================================================
// h0/c0 (transposed weights)
// ============================================================
__global__ void __launch_bounds__(256) k_h0c0(const float* __restrict__ bh0,
                                              const float* __restrict__ bc0) {
    __shared__ float xs[BSZ][128];
    int tid = threadIdx.x, lane = tid & 31, w = tid >> 5;
    int c0 = blockIdx.x*8 + (w & 1)*4;
    int b0 = (w >> 1)*8;
    float acc[4][8];
    #pragma unroll
    for (int i = 0; i < 4; i++)
        #pragma unroll
        for (int jx = 0; jx < 8; jx++) acc[i][jx] = 0.f;

    for (int kt = 0; kt < DE/128; kt++) {
        #pragma unroll
        for (int s = 0; s < 16; s++) {
            int idx = tid + s*256;
            int bb = idx >> 7, kk = idx & 127;
            int gd = kt*128 + kk;
            float m = g_meanpart[(0*BSZ + bb)*DE + gd] + g_meanpart[(1*BSZ + bb)*DE + gd]
                    + g_meanpart[(2*BSZ + bb)*DE + gd] + g_meanpart[(3*BSZ + bb)*DE + gd];
            xs[bb][kk] = m * (1.0f/PP);
        }
        __syncthreads();
        #pragma unroll
        for (int kk4 = 0; kk4 < 4; kk4++) {
            int k = kt*128 + kk4*32 + lane;
            float wv[4];
            #pragma unroll
            for (int cc = 0; cc < 4; cc++) {
                int col = c0 + cc;
                wv[cc] = (col < HH) ? g_Wh0T[(size_t)col*DE + k] : g_Wc0T[(size_t)(col - HH)*DE + k];
            }
            #pragma unroll
            for (int cc = 0; cc < 4; cc++)
                #pragma unroll
                for (int bb = 0; bb < 8; bb++)
                    acc[cc][bb] = fmaf(wv[cc], xs[b0+bb][kk4*32+lane], acc[cc][bb]);
        }
        __syncthreads();
    }
    float out = 0.f;
    #pragma unroll
    for (int cc = 0; cc < 4; cc++)
        #pragma unroll
        for (int bb = 0; bb < 8; bb++) {
            float v = acc[cc][bb];
            #pragma unroll
            for (int off = 16; off; off >>= 1) v += __shfl_xor_sync(0xffffffffu, v, off);
            if (lane == cc*8 + bb) out = v;
        }
    int cc = lane >> 3, bb = lane & 7;
    int col = c0 + cc, b = b0 + bb;
    if (col < HH) g_hbuf[b*HH + col]   = out + bh0[col];
    else          g_c[b*HH + col - HH] = out + bc0[col - HH];
}

// ============================================================
// S1: att2 = h@Wda + bda ; gate_raw = h@Wfb + bfb (transposed W)
// ============================================================
__global__ void __launch_bounds__(256) k_s1(const float* __restrict__ hcur,
                                            const float* __restrict__ bda,
                                            const float* __restrict__ bfb) {
    __shared__ float xs[BSZ][128];
    int tid = threadIdx.x, lane = tid & 31, w = tid >> 5;
    int c0 = blockIdx.x*8 + (w & 1)*4;
    int b0 = (w >> 1)*8;
    float acc[4][8];
    #pragma unroll
    for (int i = 0; i < 4; i++)
        #pragma unroll
        for (int jx = 0; jx < 8; jx++) acc[i][jx] = 0.f;

    #pragma unroll
    for (int kt = 0; kt < HH/128; kt++) {
        #pragma unroll
        for (int s = 0; s < 16; s++) {
            int idx = tid + s*256;
            int bb = idx >> 7, kk = idx & 127;
            xs[bb][kk] = hcur[bb*HH + kt*128 + kk];
        }
        __syncthreads();
        #pragma unroll
        for (int kk4 = 0; kk4 < 4; kk4++) {
            int k = kt*128 + kk4*32 + lane;
            float wv[4];
            #pragma unroll
            for (int cc = 0; cc < 4; cc++) {
                int col = c0 + cc;
                wv[cc] = (col < AA) ? g_WdaT[(size_t)col*HH + k] : g_WfbT[(size_t)(col - AA)*HH + k];
            }
            #pragma unroll
            for (int cc = 0; cc < 4; cc++)
                #pragma unroll
                for (int bb = 0; bb < 8; bb++)
                    acc[cc][bb] = fmaf(wv[cc], xs[b0+bb][kk4*32+lane], acc[cc][bb]);
        }
        __syncthreads();
    }
    float out = 0.f;
    #pragma unroll
    for (int cc = 0; cc < 4; cc++)
        #pragma unroll
        for (int bb = 0; bb < 8; bb++) {
            float v = acc[cc][bb];
            #pragma unroll
            for (int off = 16; off; off >>= 1) v += __shfl_xor_sync(0xffffffffu, v, off);
            if (lane == cc*8 + bb) out = v;
        }
    int cc = lane >> 3, bb = lane & 7;
    int col = c0 + cc, b = b0 + bb;
    if (col < AA) g_att2[b*AA + col]         = out + bda[col];
    else          g_gateraw[b*DE + col - AA] = out + bfb[col - AA];
}

// ============================================================
// S2a: scores with float4 loads. grid (25, 32) x 256
// ============================================================
__global__ void __launch_bounds__(256) k_s2a(const float* __restrict__ Wfa, const float* __restrict__ bfa) {
    int b = blockIdx.y;
    int tid = threadIdx.x, lane = tid & 31, w = tid >> 5;
    __shared__ float4 att2s4[AA/4], wfas4[AA/4];
    if (tid < AA/4) {
        att2s4[tid] = ((const float4*)(g_att2 + b*AA))[tid];
        wfas4[tid]  = ((const float4*)Wfa)[tid];
    }
    __syncthreads();
    int p = blockIdx.x*8 + w;
    if (p >= PP) return;
    const float4* row4 = (const float4*)(g_att1 + ((size_t)b*PP + p)*AA);
    float acc = 0.f;
    #pragma unroll
    for (int c = 0; c < 4; c++) {
        int idx = c*32 + lane;
        float4 v = row4[idx];
        float4 a2 = att2s4[idx];
        float4 wf = wfas4[idx];
        acc = fmaf(fmaxf(v.x + a2.x, 0.f), wf.x, acc);
        acc = fmaf(fmaxf(v.y + a2.y, 0.f), wf.y, acc);
        acc = fmaf(fmaxf(v.z + a2.z, 0.f), wf.z, acc);
        acc = fmaf(fmaxf(v.w + a2.w, 0.f), wf.w, acc);
    }
    #pragma unroll
    for (int off = 16; off; off >>= 1) acc += __shfl_xor_sync(0xffffffffu, acc, off);
    if (lane == 0) g_escore[b*PP + p] = acc + bfa[0];
}

// ============================================================
// S3f: per-block redundant softmax + awe + gate. grid (8, 32).
// ============================================================
__global__ void __launch_bounds__(256) k_s3f(int t, const float* __restrict__ feat,
                                             float* __restrict__ out_alphas) {
    int b = blockIdx.y, tid = threadIdx.x;
    __shared__ float als[PP];
    __shared__ float sred[256];
    float e = (tid < PP) ? g_escore[b*PP + tid] : -3.0e38f;
    sred[tid] = e;
    __syncthreads();
    for (int s = 128; s > 0; s >>= 1) { if (tid < s) sred[tid] = fmaxf(sred[tid], sred[tid+s]); __syncthreads(); }
    float mx = sred[0];
    __syncthreads();
    float ex = (tid < PP) ? expf(e - mx) : 0.f;
    sred[tid] = ex;
    __syncthreads();
    for (int s = 128; s > 0; s >>= 1) { if (tid < s) sred[tid] += sred[tid+s]; __syncthreads(); }
    float inv = 1.0f / sred[0];
    if (tid < PP) {
        float al = ex * inv;
        als[tid] = al;
        if (blockIdx.x == 0) {
            int active = (t < g_declen[b]);
            out_alphas[((size_t)b*TDEC + t)*PP + tid] = active ? al : 0.f;
        }
    }
    __syncthreads();

    int d = blockIdx.x*256 + tid;
    const float* base = feat + (size_t)g_sortind[b]*PP*DE + d;
    float s = 0.f;
    #pragma unroll 7
    for (int p = 0; p < PP; p++) s = fmaf(als[p], base[(size_t)p*DE], s);
    float gr = g_gateraw[b*DE + d];
    g_xawe[b*KAW + d] = sigm(gr) * s;
}

// ============================================================
// S4 fused: gates GEMM (K=2560) + LSTM cell
// ============================================================
__global__ void __launch_bounds__(256) k_s4f(int t, int cur,
        const float* __restrict__ Wih, const float* __restrict__ bih,
        const float* __restrict__ Whh, const float* __restrict__ bhh) {
    __shared__ float xs[BSZ][128];
    __shared__ float red[4][BSZ][33];
    __shared__ float gsum[16][BSZ];
    int tid = threadIdx.x, lane = tid & 31, w = tid >> 5;
    int jBlock = blockIdx.x*4;
    int r0 = (w >> 1)*4;
    int bh = (w & 1)*16;
    const float* hcur = g_hbuf + cur*BSZ*HH;
    float*       hnxt = g_hbuf + (1 - cur)*BSZ*HH;

    float acc[4][16];
    #pragma unroll
    for (int i = 0; i < 4; i++)
        #pragma unroll
        for (int jx = 0; jx < 16; jx++) acc[i][jx] = 0.f;

    const float* wrowIH[4];
    const float* wrowHH[4];
    #pragma unroll
    for (int cc = 0; cc < 4; cc++) {
        int v = r0 + cc;
        int wr = (v >> 2)*HH + jBlock + (v & 3);
        wrowIH[cc] = Wih + (size_t)wr*XX + EE;
        wrowHH[cc] = Whh + (size_t)wr*HH;
    }

    float pv[16];
    #pragma unroll
    for (int s = 0; s < 16; s++) {
        int idx = tid + s*256;
        int bb = idx >> 7, kk = idx & 127;
        pv[s] = g_xawe[bb*KAW + kk];
    }
    #pragma unroll
    for (int s = 0; s < 16; s++) {
        int idx = tid + s*256;
        xs[idx >> 7][idx & 127] = pv[s];
    }
    __syncthreads();

    for (int kt = 0; kt < KS4/128; kt++) {
        if (kt + 1 < KS4/128) {
            int gk0 = (kt + 1)*128;
            #pragma unroll
            for (int s = 0; s < 16; s++) {
                int idx = tid + s*256;
                int bb = idx >> 7, kk = idx & 127;
                int gk = gk0 + kk;
                pv[s] = (gk < KAW) ? g_xawe[bb*KAW + gk] : hcur[bb*HH + gk - KAW];
            }
        }
        #pragma unroll
        for (int kk4 = 0; kk4 < 4; kk4++) {
            int gk = kt*128 + kk4*32 + lane;
            float wv[4];
            #pragma unroll
            for (int cc = 0; cc < 4; cc++)
                wv[cc] = (gk < KAW) ? wrowIH[cc][gk] : wrowHH[cc][gk - KAW];
            #pragma unroll
            for (int bb = 0; bb < 16; bb++) {
                float xv = xs[bh + bb][kk4*32 + lane];
                #pragma unroll
                for (int cc = 0; cc < 4; cc++)
                    acc[cc][bb] = fmaf(wv[cc], xv, acc[cc][bb]);
            }
        }
        __syncthreads();
        if (kt + 1 < KS4/128) {
            #pragma unroll
            for (int s = 0; s < 16; s++) {
                int idx = tid + s*256;
                xs[idx >> 7][idx & 127] = pv[s];
            }
        }
        __syncthreads();
    }

    for (int rnd = 0; rnd < 4; rnd++) {
        if ((w >> 1) == rnd) {
            #pragma unroll
            for (int cc = 0; cc < 4; cc++)
                #pragma unroll
                for (int bb = 0; bb < 16; bb++)
                    red[cc][bh + bb][lane] = acc[cc][bb];
        }
        __syncthreads();
        if (tid < 128) {
            int cc = tid >> 5, b = tid & 31;
            float s = 0.f;
            #pragma unroll
            for (int l = 0; l < 32; l++) s += red[cc][b][l];
            gsum[rnd*4 + cc][b] = s;
        }
        __syncthreads();
    }

    if (tid < 128) {
        int jj = tid >> 5, b = tid & 31;
        int j = jBlock + jj;
        size_t pb = ((size_t)t*BSZ + b)*G4;
        float gi = gsum[0  + jj][b] + bih[0*HH + j] + bhh[0*HH + j] + g_pre[pb + 0*HH + j];
        float gf = gsum[4  + jj][b] + bih[1*HH + j] + bhh[1*HH + j] + g_pre[pb + 1*HH + j];
        float gg = gsum[8  + jj][b] + bih[2*HH + j] + bhh[2*HH + j] + g_pre[pb + 2*HH + j];
        float go = gsum[12 + jj][b] + bih[3*HH + j] + bhh[3*HH + j] + g_pre[pb + 3*HH + j];
        float c  = g_c[b*HH + j];
        float cn = sigm(gf)*c + sigm(gi)*tanhf(gg);
        float hn = sigm(go)*tanhf(cn);
        int active = (t < g_declen[b]);
        if (active) g_c[b*HH + j] = cn;
        hnxt[b*HH + j] = active ? hn : hcur[b*HH + j];
        g_Hall[((size_t)t*BSZ + b)*HH + j] = hn;
    }
}

// ============================================================
// TF32 tensor-core GEMM: 128x64 tile, BK=32, 256 threads,
// 8 warps x (32x32) warp tiles, fragment-order smem,
// double-buffered, 48KB smem.
// mode 0: embX@WihET -> pre; mode 1: att1 (A gather feat);
// mode 2: preds (A=Hall rowmap, row mask).
// ============================================================
__global__ void __launch_bounds__(256) k_gemm_tc(const float* __restrict__ Aext, int lda_,
                                                 const float* __restrict__ Bext, int ldb_,
                                                 const float* __restrict__ biasext,
                                                 float* __restrict__ Cext, int ldc_,
                                                 int M, int N, int K, int mode) {
    // A: 8 mt x 4 ks tiles of 128 floats (fragment order, XOR-swizzled chunks)
    // B: 8 nt x 4 ks tiles of 64 floats (fragment order, rotated chunks)
    __shared__ __align__(16) float Asm[2][32][128];   // 32 KB
    __shared__ __align__(16) float Bsm[2][32][64];    // 16 KB
    int tid = threadIdx.x;
    int lane = tid & 31, w = tid >> 5;
    int rowBase = blockIdx.y*128, colBase = blockIdx.x*64;

    const float* Ause; const float* Buse; const float* bias; float* Cuse;
    int lda, ldb, ldc;
    const int* rowmap = nullptr; const int* ract = nullptr;
    if (mode == 0)      { Ause = g_embX; lda = EE;   Buse = g_WihET; ldb = G4;   bias = nullptr; Cuse = g_pre;  ldc = G4; }
    else if (mode == 1) { Ause = Aext;   lda = lda_; Buse = Bext;    ldb = ldb_; bias = biasext; Cuse = g_att1; ldc = AA; rowmap = g_rowmapA; }
    else                { Ause = g_Hall; lda = HH;   Buse = Bext;    ldb = ldb_; bias = biasext; Cuse = Cext;   ldc = ldc_; rowmap = g_rowmapC; ract = g_activeC; }

    // warp tile
    int wm = w >> 1;       // 0..3  -> rows wm*32
    int wn = w & 1;        // 0..1  -> cols wn*32

    // A loader mapping
    int arow = tid >> 1;           // 0..127
    int acg  = (tid & 1) * 16;     // k-subrange 0 or 16
    int a_mt   = arow >> 4;
    int a_rlow = arow & 15;
    int a_jlo  = a_rlow >> 3;
    int a_lb   = (a_rlow & 7) * 4;
    int gRow = rowBase + arow;
    int amap = rowmap ? rowmap[gRow] : gRow;
    const float* aptr = Ause + (size_t)amap*lda;

    // B loader mapping
    int bk  = tid >> 3;            // 0..31
    int bm8 = tid & 7;             // nt
    int b_ks = bk >> 3;
    int b_kk = bk & 7;
    int b_jb = b_kk >> 2;
    int b_k3 = b_kk & 3;
    int bcol0 = colBase + bm8*8;

    float acc[2][4][4];
    #pragma unroll
    for (int mi = 0; mi < 2; mi++)
        #pragma unroll
        for (int ni = 0; ni < 4; ni++)
            #pragma unroll
            for (int e = 0; e < 4; e++) acc[mi][ni][e] = 0.f;

    float4 aR[4], bR[2];

    // ---- load chunk 0 ----
    #pragma unroll
    for (int q = 0; q < 4; q++) aR[q] = *(const float4*)(aptr + acg + q*4);
    #pragma unroll
    for (int q = 0; q < 2; q++) {
        int c = bcol0 + q*4;
        bR[q] = (c < N) ? *(const float4*)(Buse + (size_t)bk*ldb + c)
                        : make_float4(0.f,0.f,0.f,0.f);
    }
    // ---- store chunk 0 ----
    {
        #pragma unroll
        for (int q = 0; q < 4; q++) {
            int kc = acg + q*4;
            int ks = kc >> 3;
            int jhi = (kc & 4) ? 2 : 0;
            float* tb = &Asm[0][a_mt*4 + ks][0];
            int j = a_jlo + jhi;
            int c0 = a_lb + 0, c1 = a_lb + 1, c2 = a_lb + 2, c3 = a_lb + 3;
            tb[(c0 ^ (c0 >> 3))*4 + j] = __uint_as_float(f2tf32(aR[q].x));
            tb[(c1 ^ (c1 >> 3))*4 + j] = __uint_as_float(f2tf32(aR[q].y));
            tb[(c2 ^ (c2 >> 3))*4 + j] = __uint_as_float(f2tf32(aR[q].z));
            tb[(c3 ^ (c3 >> 3))*4 + j] = __uint_as_float(f2tf32(aR[q].w));
        }
        #pragma unroll
        for (int q = 0; q < 2; q++) {
            float* tb = &Bsm[0][bm8*4 + b_ks][0];
            int rot = bm8*4;
            #pragma unroll
            for (int e = 0; e < 4; e++) {
                int cc = q*4 + e;
                int ch = ((cc*4 + b_k3) + rot) & 31;
                float v = (e == 0) ? bR[q].x : (e == 1) ? bR[q].y : (e == 2) ? bR[q].z : bR[q].w;
                tb[ch*2 + b_jb] = __uint_as_float(f2tf32(v));
            }
        }
    }
    __syncthreads();

    int nch = K / 32;
    for (int ch = 0; ch < nch; ch++) {
        int buf = ch & 1;
        if (ch + 1 < nch) {
            int k0 = (ch + 1)*32;
            #pragma unroll
            for (int q = 0; q < 4; q++) aR[q] = *(const float4*)(aptr + k0 + acg + q*4);
            #pragma unroll
            for (int q = 0; q < 2; q++) {
                int c = bcol0 + q*4;
                bR[q] = (c < N) ? *(const float4*)(Buse + (size_t)(k0 + bk)*ldb + c)
                                : make_float4(0.f,0.f,0.f,0.f);
            }
        }
        // compute
        int aswl = (lane ^ (lane >> 3)) * 4;
        #pragma unroll
        for (int ks = 0; ks < 4; ks++) {
            uint4 af[2]; uint2 bf[4];
            #pragma unroll
            for (int mi = 0; mi < 2; mi++)
                af[mi] = *(const uint4*)&Asm[buf][(wm*2 + mi)*4 + ks][aswl];
            #pragma unroll
            for (int ni = 0; ni < 4; ni++) {
                int nt = wn*4 + ni;
                int chn = (lane + nt*4) & 31;
                bf[ni] = *(const uint2*)&Bsm[buf][nt*4 + ks][chn*2];
            }
            #pragma unroll
            for (int mi = 0; mi < 2; mi++)
                #pragma unroll
                for (int ni = 0; ni < 4; ni++)
                    mma_tf32(acc[mi][ni], af[mi], bf[ni]);
        }
        if (ch + 1 < nch) {
            int nb = buf ^ 1;
            #pragma unroll
            for (int q = 0; q < 4; q++) {
                int kc = acg + q*4;
                int ks = kc >> 3;
                int jhi = (kc & 4) ? 2 : 0;
                float* tb = &Asm[nb][a_mt*4 + ks][0];
                int j = a_jlo + jhi;
                int c0 = a_lb + 0, c1 = a_lb + 1, c2 = a_lb + 2, c3 = a_lb + 3;
                tb[(c0 ^ (c0 >> 3))*4 + j] = __uint_as_float(f2tf32(aR[q].x));
                tb[(c1 ^ (c1 >> 3))*4 + j] = __uint_as_float(f2tf32(aR[q].y));
                tb[(c2 ^ (c2 >> 3))*4 + j] = __uint_as_float(f2tf32(aR[q].z));
                tb[(c3 ^ (c3 >> 3))*4 + j] = __uint_as_float(f2tf32(aR[q].w));
            }
            #pragma unroll
            for (int q = 0; q < 2; q++) {
                float* tb = &Bsm[nb][bm8*4 + b_ks][0];
                int rot = bm8*4;
                #pragma unroll
                for (int e = 0; e < 4; e++) {
                    int cc = q*4 + e;
                    int ch2 = ((cc*4 + b_k3) + rot) & 31;
                    float v = (e == 0) ? bR[q].x : (e == 1) ? bR[q].y : (e == 2) ? bR[q].z : bR[q].w;
                    tb[ch2*2 + b_jb] = __uint_as_float(f2tf32(v));
                }
            }
            __syncthreads();
        }
    }

    // epilogue
    #pragma unroll
    for (int mi = 0; mi < 2; mi++) {
        int r0 = rowBase + wm*32 + mi*16 + (lane >> 2);
        int r1 = r0 + 8;
        int act0 = ract ? ract[r0] : 1;
        int act1 = ract ? ract[r1] : 1;
        #pragma unroll
        for (int ni = 0; ni < 4; ni++) {
            int col = colBase + wn*32 + ni*8 + (lane & 3)*2;
            if (col < N) {
                float b0v = bias ? bias[col]     : 0.f;
                float b1v = bias ? bias[col + 1] : 0.f;
                float2 v0, v1;
                v0.x = act0 ? (acc[mi][ni][0] + b0v) : 0.f;
                v0.y = act0 ? (acc[mi][ni][1] + b1v) : 0.f;
                v1.x = act1 ? (acc[mi][ni][2] + b0v) : 0.f;
                v1.y = act1 ? (acc[mi][ni][3] + b1v) : 0.f;
                *(float2*)&Cuse[(size_t)r0*ldc + col] = v0;
                *(float2*)&Cuse[(size_t)r1*ldc + col] = v1;
            }
        }
    }
}

// ============================================================
extern "C" void kernel_launch(void* const* d_in, const int* in_sizes, int n_in,
                              void* d_out, int out_size) {
    const float* feat     = (const float*)d_in[0];
    const int*   captions = (const int*)  d_in[1];
    const int*   caplen   = (const int*)  d_in[2];
    const float* emb      = (const float*)d_in[3];
    const float* Wea = (const float*)d_in[4];  const float* bea = (const float*)d_in[5];
    const float* Wda = (const float*)d_in[6];  const float* bda = (const float*)d_in[7];
    const float* Wfa = (const float*)d_in[8];  const float* bfa = (const float*)d_in[9];
    const float* Wih = (const float*)d_in[10]; const float* bih = (const float*)d_in[11];
    const float* Whh = (const float*)d_in[12]; const float* bhh = (const float*)d_in[13];
    const float* Wh0 = (const float*)d_in[14]; const float* bh0 = (const float*)d_in[15];
    const float* Wc0 = (const float*)d_in[16]; const float* bc0 = (const float*)d_in[17];
    const float* Wfb = (const float*)d_in[18]; const float* bfb = (const float*)d_in[19];
    const float* Wout = (const float*)d_in[20]; const float* bout = (const float*)d_in[21];

    float* out = (float*)d_out;
    float* out_pred  = out + OFF_PRED;
    float* out_alpha = out + OFF_ALPHA;
    float* out_caps  = out + OFF_CAPS;
    float* out_len   = out + OFF_LEN;
    float* out_sort  = out + OFF_SORT;

    float* hbuf_dev = nullptr;  cudaGetSymbolAddress((void**)&hbuf_dev, g_hbuf);
    float* WihET_dev = nullptr; cudaGetSymbolAddress((void**)&WihET_dev, g_WihET);
    float* WdaT_dev = nullptr;  cudaGetSymbolAddress((void**)&WdaT_dev, g_WdaT);
    float* WfbT_dev = nullptr;  cudaGetSymbolAddress((void**)&WfbT_dev, g_WfbT);
    float* Wh0T_dev = nullptr;  cudaGetSymbolAddress((void**)&Wh0T_dev, g_Wh0T);
    float* Wc0T_dev = nullptr;  cudaGetSymbolAddress((void**)&Wc0T_dev, g_Wc0T);

    // ---- prologue (att1 is the 6th launch -> ncu -s 5 -c 1 target) ----
    k_setup<<<1, 256>>>(captions, caplen, out_caps, out_len, out_sort);          // 1
    k_embgather<<<dim3(TDEC, BSZ), 128>>>(emb);                                  // 2
    k_trans<<<dim3(2048/32, 512/32), 256>>>(Wih, XX, WihET_dev, G4);             // 3
    k_trans<<<dim3(512/32, 512/32),  256>>>(Wda, AA, WdaT_dev, HH);              // 4
    k_trans<<<dim3(512/32, 2048/32), 256>>>(Wfb, DE, WfbT_dev, HH);              // 5
    // att1 = enc @ Wea + bea : M=6272, N=512, K=2048
    k_gemm_tc<<<dim3(AA/64, (BSZ*PP)/128), 256>>>(feat, DE, Wea, AA, bea,        // 6 (profiled)
                                                  nullptr, 0, BSZ*PP, AA, DE, 1);
    k_trans<<<dim3(2048/32, 512/32), 256>>>(Wh0, HH, Wh0T_dev, DE);              // 7
    k_trans<<<dim3(2048/32, 512/32), 256>>>(Wc0, HH, Wc0T_dev, DE);              // 8
    k_meanpart<<<dim3(DE/256, BSZ, 4), 256>>>(feat);                             // 9
    k_h0c0<<<128, 256>>>(bh0, bc0);                                              // 10
    // pre = embX @ WihET : M=640, N=2048, K=512
    k_gemm_tc<<<dim3(G4/64, (TDEC*BSZ)/128), 256>>>(nullptr, 0, nullptr, 0, nullptr,
                                                    nullptr, 0, TDEC*BSZ, G4, EE, 0);

    // ---- recurrence (round-4 structure: best known) ----
    for (int t = 0; t < TDEC; t++) {
        int cur = t & 1;
        const float* hcur = hbuf_dev + cur*BSZ*HH;
        k_s1<<<XX/8, 256>>>(hcur, bda, bfb);
        k_s2a<<<dim3((PP + 7)/8, BSZ), 256>>>(Wfa, bfa);
        k_s3f<<<dim3(DE/256, BSZ), 256>>>(t, feat, out_alpha);
        k_s4f<<<HH/4, 256>>>(t, cur, Wih, bih, Whh, bhh);
    }

    // ---- epilogue: preds = Hall @ Wout + bout : M=640, N=30000, K=512 ----
    k_gemm_tc<<<dim3((VV + 63)/64, (TDEC*BSZ)/128), 256>>>(nullptr, 0, Wout, VV, bout,
                                                           out_pred, VV, TDEC*BSZ, VV, HH, 2);
}

// round 7
// speedup vs baseline: 1.4309x; 1.0510x over previous
#include <cuda_runtime.h>
#include <math.h>

// ---- problem constants ----
#define BSZ   32
#define TT    22
#define PP    196
#define DE    2048
#define EE    512
#define HH    512
#define AA    512
#define VV    30000
#define TDEC  20
#define XX    2560   // E + DE
#define G4    2048   // 4*H
#define KAW   2048   // awe part of K in LSTM gemm
#define KS4   2560   // awe + h

// ---- output layout ----
#define OFF_PRED  0
#define OFF_ALPHA (BSZ*TDEC*VV)
#define OFF_CAPS  (OFF_ALPHA + BSZ*TDEC*PP)
#define OFF_LEN   (OFF_CAPS + BSZ*TT)
#define OFF_SORT  (OFF_LEN + BSZ)

// ---- device scratch ----
__device__ float g_att1[BSZ*PP*AA];
__device__ float g_hbuf[2*BSZ*HH];
__device__ float g_c[BSZ*HH];
__device__ float g_att2[BSZ*AA];
__device__ float g_gateraw[BSZ*DE];
__device__ float g_escore[BSZ*PP];
__device__ float g_xawe[BSZ*KAW];
__device__ float g_Hall[TDEC*BSZ*HH];
__device__ float g_meanpart[4*BSZ*DE];
__device__ float g_embX[TDEC*BSZ*EE];
__device__ float g_WihET[EE*G4];
__device__ float g_pre[TDEC*BSZ*G4];
__device__ float g_WdaT[AA*HH];
__device__ float g_WfbT[DE*HH];
__device__ float g_Wh0T[HH*DE];
__device__ float g_Wc0T[HH*DE];
__device__ int   g_sortind[BSZ];
__device__ int   g_declen[BSZ];
__device__ int   g_caps[BSZ*TT];
__device__ int   g_rowmapA[BSZ*PP];
__device__ int   g_rowmapC[BSZ*TDEC];
__device__ int   g_activeC[BSZ*TDEC];

__device__ __forceinline__ float sigm(float x) { return 1.0f / (1.0f + expf(-x)); }

__device__ __forceinline__ unsigned f2tf32(float f) {
    unsigned r;
    asm("cvt.rna.tf32.f32 %0, %1;" : "=r"(r) : "f"(f));
    return r;
}

__device__ __forceinline__ void mma_tf32(float* d, const uint4& a, const uint2& b) {
    asm("mma.sync.aligned.m16n8k8.row.col.f32.tf32.tf32.f32 "
        "{%0,%1,%2,%3},{%4,%5,%6,%7},{%8,%9},{%0,%1,%2,%3};"
        : "+f"(d[0]), "+f"(d[1]), "+f"(d[2]), "+f"(d[3])
        : "r"(a.x), "r"(a.y), "r"(a.z), "r"(a.w), "r"(b.x), "r"(b.y));
}

// ============================================================
// Setup
// ============================================================
__global__ void k_setup(const int* __restrict__ captions,
                        const int* __restrict__ cap_len,
                        float* __restrict__ out_caps,
                        float* __restrict__ out_len,
                        float* __restrict__ out_sort) {
    int tid = threadIdx.x;
    __shared__ int s_len[BSZ];
    __shared__ int s_sort[BSZ];
    __shared__ int s_dec[BSZ];
    if (tid < BSZ) s_len[tid] = cap_len[tid];
    __syncthreads();
    if (tid < BSZ) {
        int li = s_len[tid];
        int rank = 0;
        for (int j = 0; j < BSZ; j++) {
            int lj = s_len[j];
            if (lj > li || (lj == li && j < tid)) rank++;
        }
        s_sort[rank] = tid;
    }
    __syncthreads();
    if (tid < BSZ) {
        int src = s_sort[tid];
        g_sortind[tid] = src;
        int L = s_len[src];
        g_declen[tid] = L - 1;
        s_dec[tid]    = L - 1;
        out_len[tid]  = (float)L;
        out_sort[tid] = (float)src;
    }
    __syncthreads();
    for (int i = tid; i < BSZ*TT; i += blockDim.x) {
        int b = i / TT, t = i % TT;
        int v = captions[t*BSZ + s_sort[b]];
        g_caps[i] = v;
        out_caps[i] = (float)v;
    }
    for (int i = tid; i < BSZ*PP; i += blockDim.x) {
        int b = i / PP, p = i % PP;
        g_rowmapA[i] = s_sort[b]*PP + p;
    }
    for (int i = tid; i < BSZ*TDEC; i += blockDim.x) {
        int b = i / TDEC, t = i % TDEC;
        g_rowmapC[i] = t*BSZ + b;
        g_activeC[i] = (t < s_dec[b]) ? 1 : 0;
    }
}

// ============================================================
// Gather embeddings
// ============================================================
__global__ void k_embgather(const float* __restrict__ emb) {
    int t = blockIdx.x, b = blockIdx.y;
    int tok = g_caps[b*TT + t];
    const float* src = emb + (size_t)tok*EE;
    float* dst = g_embX + ((size_t)t*BSZ + b)*EE;
    for (int e = threadIdx.x; e < EE; e += blockDim.x) dst[e] = src[e];
}

// ============================================================
// Transpose
// ============================================================
__global__ void __launch_bounds__(256) k_trans(const float* __restrict__ src, int srcLd,
                                               float* __restrict__ dst, int dstLd) {
    __shared__ float ts[32][33];
    int r0 = blockIdx.x*32, c0 = blockIdx.y*32;
    int tx = threadIdx.x & 31, ty = threadIdx.x >> 5;
    #pragma unroll
    for (int rr = ty; rr < 32; rr += 8)
        ts[rr][tx] = src[(size_t)(r0 + rr)*srcLd + c0 + tx];
    __syncthreads();
    #pragma unroll
    for (int rr = ty; rr < 32; rr += 8)
        dst[(size_t)(c0 + rr)*dstLd + r0 + tx] = ts[tx][rr];
}

// ============================================================
// mean partials
// ============================================================
__global__ void k_meanpart(const float* __restrict__ feat) {
    int b = blockIdx.y, ps = blockIdx.z;
    int d = blockIdx.x*256 + threadIdx.x;
    const float* base = feat + (size_t)g_sortind[b]*PP*DE + d;
    float s = 0.f;
    int p0 = ps*49;
    #pragma unroll 7
    for (int p = p0; p < p0 + 49; p++) s += base[(size_t)p*DE];
    g_meanpart[((ps*BSZ) + b)*DE + d] = s;
}

// ============================================================
// h0/c0 (transposed weights)
// ============================================================
__global__ void __launch_bounds__(256) k_h0c0(const float* __restrict__ bh0,
                                              const float* __restrict__ bc0) {
    __shared__ float xs[BSZ][128];
    int tid = threadIdx.x, lane = tid & 31, w = tid >> 5;
    int c0 = blockIdx.x*8 + (w & 1)*4;
    int b0 = (w >> 1)*8;
    float acc[4][8];
    #pragma unroll
    for (int i = 0; i < 4; i++)
        #pragma unroll
        for (int jx = 0; jx < 8; jx++) acc[i][jx] = 0.f;

    for (int kt = 0; kt < DE/128; kt++) {
        #pragma unroll
        for (int s = 0; s < 16; s++) {
            int idx = tid + s*256;
            int bb = idx >> 7, kk = idx & 127;
            int gd = kt*128 + kk;
            float m = g_meanpart[(0*BSZ + bb)*DE + gd] + g_meanpart[(1*BSZ + bb)*DE + gd]
                    + g_meanpart[(2*BSZ + bb)*DE + gd] + g_meanpart[(3*BSZ + bb)*DE + gd];
            xs[bb][kk] = m * (1.0f/PP);
        }
        __syncthreads();
        #pragma unroll
        for (int kk4 = 0; kk4 < 4; kk4++) {
            int k = kt*128 + kk4*32 + lane;
            float wv[4];
            #pragma unroll
            for (int cc = 0; cc < 4; cc++) {
                int col = c0 + cc;
                wv[cc] = (col < HH) ? g_Wh0T[(size_t)col*DE + k] : g_Wc0T[(size_t)(col - HH)*DE + k];
            }
            #pragma unroll
            for (int cc = 0; cc < 4; cc++)
                #pragma unroll
                for (int bb = 0; bb < 8; bb++)
                    acc[cc][bb] = fmaf(wv[cc], xs[b0+bb][kk4*32+lane], acc[cc][bb]);
        }
        __syncthreads();
    }
    float out = 0.f;
    #pragma unroll
    for (int cc = 0; cc < 4; cc++)
        #pragma unroll
        for (int bb = 0; bb < 8; bb++) {
            float v = acc[cc][bb];
            #pragma unroll
            for (int off = 16; off; off >>= 1) v += __shfl_xor_sync(0xffffffffu, v, off);
            if (lane == cc*8 + bb) out = v;
        }
    int cc = lane >> 3, bb = lane & 7;
    int col = c0 + cc, b = b0 + bb;
    if (col < HH) g_hbuf[b*HH + col]   = out + bh0[col];
    else          g_c[b*HH + col - HH] = out + bc0[col - HH];
}

// ============================================================
// S1 (PDL): preamble loads weights to smem, gridsync, then h.
// ============================================================
__global__ void __launch_bounds__(256) k_s1(const float* __restrict__ hcur,
                                            const float* __restrict__ bda,
                                            const float* __restrict__ bfb) {
    __shared__ float ws[8][HH];     // 16KB weight slice
    __shared__ float xs[BSZ][128];  // 16KB
    int tid = threadIdx.x, lane = tid & 31, w = tid >> 5;
    int cbase = blockIdx.x*8;

    // ---- preamble (independent of predecessor) ----
    {
        int cc = tid >> 5;           // 0..7
        int k0 = (tid & 31)*16;
        int col = cbase + cc;
        const float* src = (col < AA) ? (g_WdaT + (size_t)col*HH)
                                      : (g_WfbT + (size_t)(col - AA)*HH);
        #pragma unroll
        for (int q = 0; q < 4; q++)
            *(float4*)&ws[cc][k0 + q*4] = *(const float4*)(src + k0 + q*4);
    }

    cudaGridDependencySynchronize();

    int c0l = (w & 1)*4;            // local weight row base
    int b0 = (w >> 1)*8;
    float acc[4][8];
    #pragma unroll
    for (int i = 0; i < 4; i++)
        #pragma unroll
        for (int jx = 0; jx < 8; jx++) acc[i][jx] = 0.f;

    #pragma unroll
    for (int kt = 0; kt < HH/128; kt++) {
        #pragma unroll
        for (int s = 0; s < 16; s++) {
            int idx = tid + s*256;
            int bb = idx >> 7, kk = idx & 127;
            xs[bb][kk] = hcur[bb*HH + kt*128 + kk];
        }
        __syncthreads();
        #pragma unroll
        for (int kk4 = 0; kk4 < 4; kk4++) {
            int k = kt*128 + kk4*32 + lane;
            float wv[4];
            #pragma unroll
            for (int cc = 0; cc < 4; cc++) wv[cc] = ws[c0l + cc][k];
            #pragma unroll
            for (int cc = 0; cc < 4; cc++)
                #pragma unroll
                for (int bb = 0; bb < 8; bb++)
                    acc[cc][bb] = fmaf(wv[cc], xs[b0+bb][kk4*32+lane], acc[cc][bb]);
        }
        __syncthreads();
    }
    float out = 0.f;
    #pragma unroll
    for (int cc = 0; cc < 4; cc++)
        #pragma unroll
        for (int bb = 0; bb < 8; bb++) {
            float v = acc[cc][bb];
            #pragma unroll
            for (int off = 16; off; off >>= 1) v += __shfl_xor_sync(0xffffffffu, v, off);
            if (lane == cc*8 + bb) out = v;
        }
    cudaTriggerProgrammaticLaunchCompletion();
    int cc = lane >> 3, bb = lane & 7;
    int col = cbase + c0l + cc, b = b0 + bb;
    if (col < AA) g_att2[b*AA + col]         = out + bda[col];
    else          g_gateraw[b*DE + col - AA] = out + bfb[col - AA];
}

// ============================================================
// S2a (PDL): preamble loads att1 fragment (stable) + Wfa,
// gridsync, then att2.
// ============================================================
__global__ void __launch_bounds__(256) k_s2a(const float* __restrict__ Wfa, const float* __restrict__ bfa) {
    int b = blockIdx.y;
    int tid = threadIdx.x, lane = tid & 31, w = tid >> 5;
    __shared__ float4 att2s4[AA/4], wfas4[AA/4];
    int p = blockIdx.x*8 + w;
    bool pvld = (p < PP);
    int psafe = pvld ? p : (PP - 1);

    // ---- preamble ----
    float4 v[4];
    {
        const float4* row4 = (const float4*)(g_att1 + ((size_t)b*PP + psafe)*AA);
        #pragma unroll
        for (int c = 0; c < 4; c++) v[c] = row4[c*32 + lane];
        if (tid < AA/4) wfas4[tid] = ((const float4*)Wfa)[tid];
    }
    float bfa0 = bfa[0];

    cudaGridDependencySynchronize();

    if (tid < AA/4) att2s4[tid] = ((const float4*)(g_att2 + b*AA))[tid];
    __syncthreads();

    float acc = 0.f;
    #pragma unroll
    for (int c = 0; c < 4; c++) {
        int idx = c*32 + lane;
        float4 a2 = att2s4[idx];
        float4 wf = wfas4[idx];
        acc = fmaf(fmaxf(v[c].x + a2.x, 0.f), wf.x, acc);
        acc = fmaf(fmaxf(v[c].y + a2.y, 0.f), wf.y, acc);
        acc = fmaf(fmaxf(v[c].z + a2.z, 0.f), wf.z, acc);
        acc = fmaf(fmaxf(v[c].w + a2.w, 0.f), wf.w, acc);
    }
    #pragma unroll
    for (int off = 16; off; off >>= 1) acc += __shfl_xor_sync(0xffffffffu, acc, off);
    cudaTriggerProgrammaticLaunchCompletion();
    if (pvld && lane == 0) g_escore[b*PP + p] = acc + bfa0;
}

// ============================================================
// S3f (PDL): gridsync at top; softmax + awe + gate.
// ============================================================
__global__ void __launch_bounds__(256) k_s3f(int t, const float* __restrict__ feat,
                                             float* __restrict__ out_alphas) {
    int b = blockIdx.y, tid = threadIdx.x;
    __shared__ float als[PP];
    __shared__ float sred[256];

    cudaGridDependencySynchronize();

    float e = (tid < PP) ? g_escore[b*PP + tid] : -3.0e38f;
    sred[tid] = e;
    __syncthreads();
    for (int s = 128; s > 0; s >>= 1) { if (tid < s) sred[tid] = fmaxf(sred[tid], sred[tid+s]); __syncthreads(); }
    float mx = sred[0];
    __syncthreads();
    float ex = (tid < PP) ? expf(e - mx) : 0.f;
    sred[tid] = ex;
    __syncthreads();
    for (int s = 128; s > 0; s >>= 1) { if (tid < s) sred[tid] += sred[tid+s]; __syncthreads(); }
    float inv = 1.0f / sred[0];
    if (tid < PP) {
        float al = ex * inv;
        als[tid] = al;
        if (blockIdx.x == 0) {
            int active = (t < g_declen[b]);
            out_alphas[((size_t)b*TDEC + t)*PP + tid] = active ? al : 0.f;
        }
    }
    __syncthreads();

    cudaTriggerProgrammaticLaunchCompletion();

    int d = blockIdx.x*256 + tid;
    const float* base = feat + (size_t)g_sortind[b]*PP*DE + d;
    float s = 0.f;
    #pragma unroll 7
    for (int p = 0; p < PP; p++) s = fmaf(als[p], base[(size_t)p*DE], s);
    float gr = g_gateraw[b*DE + d];
    g_xawe[b*KAW + d] = sigm(gr) * s;
}

// ============================================================
// S4f (PDL): gridsync before xawe; gates GEMM + LSTM cell.
// ============================================================
__global__ void __launch_bounds__(256) k_s4f(int t, int cur,
        const float* __restrict__ Wih, const float* __restrict__ bih,
        const float* __restrict__ Whh, const float* __restrict__ bhh) {
    __shared__ float xs[BSZ][128];
    __shared__ float red[4][BSZ][33];
    __shared__ float gsum[16][BSZ];
    int tid = threadIdx.x, lane = tid & 31, w = tid >> 5;
    int jBlock = blockIdx.x*4;
    int r0 = (w >> 1)*4;
    int bh = (w & 1)*16;
    const float* hcur = g_hbuf + cur*BSZ*HH;
    float*       hnxt = g_hbuf + (1 - cur)*BSZ*HH;

    float acc[4][16];
    #pragma unroll
    for (int i = 0; i < 4; i++)
        #pragma unroll
        for (int jx = 0; jx < 16; jx++) acc[i][jx] = 0.f;

    const float* wrowIH[4];
    const float* wrowHH[4];
    #pragma unroll
    for (int cc = 0; cc < 4; cc++) {
        int v = r0 + cc;
        int wr = (v >> 2)*HH + jBlock + (v & 3);
        wrowIH[cc] = Wih + (size_t)wr*XX + EE;
        wrowHH[cc] = Whh + (size_t)wr*HH;
    }

    cudaGridDependencySynchronize();

    float pv[16];
    #pragma unroll
    for (int s = 0; s < 16; s++) {
        int idx = tid + s*256;
        int bb = idx >> 7, kk = idx & 127;
        pv[s] = g_xawe[bb*KAW + kk];
    }
    #pragma unroll
    for (int s = 0; s < 16; s++) {
        int idx = tid + s*256;
        xs[idx >> 7][idx & 127] = pv[s];
    }
    __syncthreads();

    for (int kt = 0; kt < KS4/128; kt++) {
        if (kt + 1 < KS4/128) {
            int gk0 = (kt + 1)*128;
            #pragma unroll
            for (int s = 0; s < 16; s++) {
                int idx = tid + s*256;
                int bb = idx >> 7, kk = idx & 127;
                int gk = gk0 + kk;
                pv[s] = (gk < KAW) ? g_xawe[bb*KAW + gk] : hcur[bb*HH + gk - KAW];
            }
        }
        #pragma unroll
        for (int kk4 = 0; kk4 < 4; kk4++) {
            int gk = kt*128 + kk4*32 + lane;
            float wv[4];
            #pragma unroll
            for (int cc = 0; cc < 4; cc++)
                wv[cc] = (gk < KAW) ? wrowIH[cc][gk] : wrowHH[cc][gk - KAW];
            #pragma unroll
            for (int bb = 0; bb < 16; bb++) {
                float xv = xs[bh + bb][kk4*32 + lane];
                #pragma unroll
                for (int cc = 0; cc < 4; cc++)
                    acc[cc][bb] = fmaf(wv[cc], xv, acc[cc][bb]);
            }
        }
        __syncthreads();
        if (kt + 1 < KS4/128) {
            #pragma unroll
            for (int s = 0; s < 16; s++) {
                int idx = tid + s*256;
                xs[idx >> 7][idx & 127] = pv[s];
            }
        }
        __syncthreads();
    }

    for (int rnd = 0; rnd < 4; rnd++) {
        if ((w >> 1) == rnd) {
            #pragma unroll
            for (int cc = 0; cc < 4; cc++)
                #pragma unroll
                for (int bb = 0; bb < 16; bb++)
                    red[cc][bh + bb][lane] = acc[cc][bb];
        }
        __syncthreads();
        if (tid < 128) {
            int cc = tid >> 5, b = tid & 31;
            float s = 0.f;
            #pragma unroll
            for (int l = 0; l < 32; l++) s += red[cc][b][l];
            gsum[rnd*4 + cc][b] = s;
        }
        __syncthreads();
    }

    cudaTriggerProgrammaticLaunchCompletion();

    if (tid < 128) {
        int jj = tid >> 5, b = tid & 31;
        int j = jBlock + jj;
        size_t pb = ((size_t)t*BSZ + b)*G4;
        float gi = gsum[0  + jj][b] + bih[0*HH + j] + bhh[0*HH + j] + g_pre[pb + 0*HH + j];
        float gf = gsum[4  + jj][b] + bih[1*HH + j] + bhh[1*HH + j] + g_pre[pb + 1*HH + j];
        float gg = gsum[8  + jj][b] + bih[2*HH + j] + bhh[2*HH + j] + g_pre[pb + 2*HH + j];
        float go = gsum[12 + jj][b] + bih[3*HH + j] + bhh[3*HH + j] + g_pre[pb + 3*HH + j];
        float c  = g_c[b*HH + j];
        float cn = sigm(gf)*c + sigm(gi)*tanhf(gg);
        float hn = sigm(go)*tanhf(cn);
        int active = (t < g_declen[b]);
        if (active) g_c[b*HH + j] = cn;
        hnxt[b*HH + j] = active ? hn : hcur[b*HH + j];
        g_Hall[((size_t)t*BSZ + b)*HH + j] = hn;
    }
}

// ============================================================
// TF32 tensor-core GEMM (mode 2 gains PDL gridsync before A).
// ============================================================
__global__ void __launch_bounds__(256) k_gemm_tc(const float* __restrict__ Aext, int lda_,
                                                 const float* __restrict__ Bext, int ldb_,
                                                 const float* __restrict__ biasext,
                                                 float* __restrict__ Cext, int ldc_,
                                                 int M, int N, int K, int mode) {
    __shared__ __align__(16) float Asm[2][32][128];
    __shared__ __align__(16) float Bsm[2][32][64];
    int tid = threadIdx.x;
    int lane = tid & 31, w = tid >> 5;
    int rowBase = blockIdx.y*128, colBase = blockIdx.x*64;

    const float* Ause; const float* Buse; const float* bias; float* Cuse;
    int lda, ldb, ldc;
    const int* rowmap = nullptr; const int* ract = nullptr;
    if (mode == 0)      { Ause = g_embX; lda = EE;   Buse = g_WihET; ldb = G4;   bias = nullptr; Cuse = g_pre;  ldc = G4; }
    else if (mode == 1) { Ause = Aext;   lda = lda_; Buse = Bext;    ldb = ldb_; bias = biasext; Cuse = g_att1; ldc = AA; rowmap = g_rowmapA; }
    else                { Ause = g_Hall; lda = HH;   Buse = Bext;    ldb = ldb_; bias = biasext; Cuse = Cext;   ldc = ldc_; rowmap = g_rowmapC; ract = g_activeC; }

    int wm = w >> 1;
    int wn = w & 1;

    int arow = tid >> 1;
    int acg  = (tid & 1) * 16;
    int a_mt   = arow >> 4;
    int a_rlow = arow & 15;
    int a_jlo  = a_rlow >> 3;
    int a_lb   = (a_rlow & 7) * 4;
    int gRow = rowBase + arow;
    int amap = rowmap ? rowmap[gRow] : gRow;
    const float* aptr = Ause + (size_t)amap*lda;

    int bk  = tid >> 3;
    int bm8 = tid & 7;
    int b_ks = bk >> 3;
    int b_kk = bk & 7;
    int b_jb = b_kk >> 2;
    int b_k3 = b_kk & 3;
    int bcol0 = colBase + bm8*8;

    float acc[2][4][4];
    #pragma unroll
    for (int mi = 0; mi < 2; mi++)
        #pragma unroll
        for (int ni = 0; ni < 4; ni++)
            #pragma unroll
            for (int e = 0; e < 4; e++) acc[mi][ni][e] = 0.f;

    float4 aR[4], bR[2];

    // ---- load chunk 0: B (stable) first, sync, then A ----
    #pragma unroll
    for (int q = 0; q < 2; q++) {
        int c = bcol0 + q*4;
        bR[q] = (c < N) ? *(const float4*)(Buse + (size_t)bk*ldb + c)
                        : make_float4(0.f,0.f,0.f,0.f);
    }
    if (mode == 2) cudaGridDependencySynchronize();
    #pragma unroll
    for (int q = 0; q < 4; q++) aR[q] = *(const float4*)(aptr + acg + q*4);
    {
        #pragma unroll
        for (int q = 0; q < 4; q++) {
            int kc = acg + q*4;
            int ks = kc >> 3;
            int jhi = (kc & 4) ? 2 : 0;
            float* tb = &Asm[0][a_mt*4 + ks][0];
            int j = a_jlo + jhi;
            int c0 = a_lb + 0, c1 = a_lb + 1, c2 = a_lb + 2, c3 = a_lb + 3;
            tb[(c0 ^ (c0 >> 3))*4 + j] = __uint_as_float(f2tf32(aR[q].x));
            tb[(c1 ^ (c1 >> 3))*4 + j] = __uint_as_float(f2tf32(aR[q].y));
            tb[(c2 ^ (c2 >> 3))*4 + j] = __uint_as_float(f2tf32(aR[q].z));
            tb[(c3 ^ (c3 >> 3))*4 + j] = __uint_as_float(f2tf32(aR[q].w));
        }
        #pragma unroll
        for (int q = 0; q < 2; q++) {
            float* tb = &Bsm[0][bm8*4 + b_ks][0];
            int rot = bm8*4;
            #pragma unroll
            for (int e = 0; e < 4; e++) {
                int cc = q*4 + e;
                int ch = ((cc*4 + b_k3) + rot) & 31;
                float v = (e == 0) ? bR[q].x : (e == 1) ? bR[q].y : (e == 2) ? bR[q].z : bR[q].w;
                tb[ch*2 + b_jb] = __uint_as_float(f2tf32(v));
            }
        }
    }
    __syncthreads();

    int nch = K / 32;
    for (int ch = 0; ch < nch; ch++) {
        int buf = ch & 1;
        if (ch + 1 < nch) {
            int k0 = (ch + 1)*32;
            #pragma unroll
            for (int q = 0; q < 4; q++) aR[q] = *(const float4*)(aptr + k0 + acg + q*4);
            #pragma unroll
            for (int q = 0; q < 2; q++) {
                int c = bcol0 + q*4;
                bR[q] = (c < N) ? *(const float4*)(Buse + (size_t)(k0 + bk)*ldb + c)
                                : make_float4(0.f,0.f,0.f,0.f);
            }
        }
        int aswl = (lane ^ (lane >> 3)) * 4;
        #pragma unroll
        for (int ks = 0; ks < 4; ks++) {
            uint4 af[2]; uint2 bf[4];
            #pragma unroll
            for (int mi = 0; mi < 2; mi++)
                af[mi] = *(const uint4*)&Asm[buf][(wm*2 + mi)*4 + ks][aswl];
            #pragma unroll
            for (int ni = 0; ni < 4; ni++) {
                int nt = wn*4 + ni;
                int chn = (lane + nt*4) & 31;
                bf[ni] = *(const uint2*)&Bsm[buf][nt*4 + ks][chn*2];
            }
            #pragma unroll
            for (int mi = 0; mi < 2; mi++)
                #pragma unroll
                for (int ni = 0; ni < 4; ni++)
                    mma_tf32(acc[mi][ni], af[mi], bf[ni]);
        }
        if (ch + 1 < nch) {
            int nb = buf ^ 1;
            #pragma unroll
            for (int q = 0; q < 4; q++) {
                int kc = acg + q*4;
                int ks = kc >> 3;
                int jhi = (kc & 4) ? 2 : 0;
                float* tb = &Asm[nb][a_mt*4 + ks][0];
                int j = a_jlo + jhi;
                int c0 = a_lb + 0, c1 = a_lb + 1, c2 = a_lb + 2, c3 = a_lb + 3;
                tb[(c0 ^ (c0 >> 3))*4 + j] = __uint_as_float(f2tf32(aR[q].x));
                tb[(c1 ^ (c1 >> 3))*4 + j] = __uint_as_float(f2tf32(aR[q].y));
                tb[(c2 ^ (c2 >> 3))*4 + j] = __uint_as_float(f2tf32(aR[q].z));
                tb[(c3 ^ (c3 >> 3))*4 + j] = __uint_as_float(f2tf32(aR[q].w));
            }
            #pragma unroll
            for (int q = 0; q < 2; q++) {
                float* tb = &Bsm[nb][bm8*4 + b_ks][0];
                int rot = bm8*4;
                #pragma unroll
                for (int e = 0; e < 4; e++) {
                    int cc = q*4 + e;
                    int ch2 = ((cc*4 + b_k3) + rot) & 31;
                    float v = (e == 0) ? bR[q].x : (e == 1) ? bR[q].y : (e == 2) ? bR[q].z : bR[q].w;
                    tb[ch2*2 + b_jb] = __uint_as_float(f2tf32(v));
                }
            }
            __syncthreads();
        }
    }

    #pragma unroll
    for (int mi = 0; mi < 2; mi++) {
        int r0 = rowBase + wm*32 + mi*16 + (lane >> 2);
        int r1 = r0 + 8;
        int act0 = ract ? ract[r0] : 1;
        int act1 = ract ? ract[r1] : 1;
        #pragma unroll
        for (int ni = 0; ni < 4; ni++) {
            int col = colBase + wn*32 + ni*8 + (lane & 3)*2;
            if (col < N) {
                float b0v = bias ? bias[col]     : 0.f;
                float b1v = bias ? bias[col + 1] : 0.f;
                float2 v0, v1;
                v0.x = act0 ? (acc[mi][ni][0] + b0v) : 0.f;
                v0.y = act0 ? (acc[mi][ni][1] + b1v) : 0.f;
                v1.x = act1 ? (acc[mi][ni][2] + b0v) : 0.f;
                v1.y = act1 ? (acc[mi][ni][3] + b1v) : 0.f;
                *(float2*)&Cuse[(size_t)r0*ldc + col] = v0;
                *(float2*)&Cuse[(size_t)r1*ldc + col] = v1;
            }
        }
    }
}

// ============================================================
// host-side PDL launch helper
// ============================================================
template <typename F, typename... Args>
static inline void launch_pdl(F kernel, dim3 grid, dim3 block, Args... args) {
    cudaLaunchConfig_t cfg = {};
    cfg.gridDim = grid;
    cfg.blockDim = block;
    cudaLaunchAttribute attr[1];
    attr[0].id = cudaLaunchAttributeProgrammaticStreamSerialization;
    attr[0].val.programmaticStreamSerializationAllowed = 1;
    cfg.attrs = attr;
    cfg.numAttrs = 1;
    cudaLaunchKernelEx(&cfg, kernel, args...);
}

// ============================================================
extern "C" void kernel_launch(void* const* d_in, const int* in_sizes, int n_in,
                              void* d_out, int out_size) {
    const float* feat     = (const float*)d_in[0];
    const int*   captions = (const int*)  d_in[1];
    const int*   caplen   = (const int*)  d_in[2];
    const float* emb      = (const float*)d_in[3];
    const float* Wea = (const float*)d_in[4];  const float* bea = (const float*)d_in[5];
    const float* Wda = (const float*)d_in[6];  const float* bda = (const float*)d_in[7];
    const float* Wfa = (const float*)d_in[8];  const float* bfa = (const float*)d_in[9];
    const float* Wih = (const float*)d_in[10]; const float* bih = (const float*)d_in[11];
    const float* Whh = (const float*)d_in[12]; const float* bhh = (const float*)d_in[13];
    const float* Wh0 = (const float*)d_in[14]; const float* bh0 = (const float*)d_in[15];
    const float* Wc0 = (const float*)d_in[16]; const float* bc0 = (const float*)d_in[17];
    const float* Wfb = (const float*)d_in[18]; const float* bfb = (const float*)d_in[19];
    const float* Wout = (const float*)d_in[20]; const float* bout = (const float*)d_in[21];

    float* out = (float*)d_out;
    float* out_pred  = out + OFF_PRED;
    float* out_alpha = out + OFF_ALPHA;
    float* out_caps  = out + OFF_CAPS;
    float* out_len   = out + OFF_LEN;
    float* out_sort  = out + OFF_SORT;

    float* hbuf_dev = nullptr;  cudaGetSymbolAddress((void**)&hbuf_dev, g_hbuf);
    float* WihET_dev = nullptr; cudaGetSymbolAddress((void**)&WihET_dev, g_WihET);
    float* WdaT_dev = nullptr;  cudaGetSymbolAddress((void**)&WdaT_dev, g_WdaT);
    float* WfbT_dev = nullptr;  cudaGetSymbolAddress((void**)&WfbT_dev, g_WfbT);
    float* Wh0T_dev = nullptr;  cudaGetSymbolAddress((void**)&Wh0T_dev, g_Wh0T);
    float* Wc0T_dev = nullptr;  cudaGetSymbolAddress((void**)&Wc0T_dev, g_Wc0T);

    // ---- prologue (att1 is the 6th launch -> ncu -s 5 -c 1 target) ----
    k_setup<<<1, 256>>>(captions, caplen, out_caps, out_len, out_sort);          // 1
    k_embgather<<<dim3(TDEC, BSZ), 128>>>(emb);                                  // 2
    k_trans<<<dim3(2048/32, 512/32), 256>>>(Wih, XX, WihET_dev, G4);             // 3
    k_trans<<<dim3(512/32, 512/32),  256>>>(Wda, AA, WdaT_dev, HH);              // 4
    k_trans<<<dim3(512/32, 2048/32), 256>>>(Wfb, DE, WfbT_dev, HH);              // 5
    // att1 = enc @ Wea + bea : M=6272, N=512, K=2048
    k_gemm_tc<<<dim3(AA/64, (BSZ*PP)/128), 256>>>(feat, DE, Wea, AA, bea,        // 6 (profiled)
                                                  nullptr, 0, BSZ*PP, AA, DE, 1);
    k_trans<<<dim3(2048/32, 512/32), 256>>>(Wh0, HH, Wh0T_dev, DE);              // 7
    k_trans<<<dim3(2048/32, 512/32), 256>>>(Wc0, HH, Wc0T_dev, DE);              // 8
    k_meanpart<<<dim3(DE/256, BSZ, 4), 256>>>(feat);                             // 9
    k_h0c0<<<128, 256>>>(bh0, bc0);                                              // 10
    // pre = embX @ WihET : M=640, N=2048, K=512
    k_gemm_tc<<<dim3(G4/64, (TDEC*BSZ)/128), 256>>>(nullptr, 0, nullptr, 0, nullptr,
                                                    nullptr, 0, TDEC*BSZ, G4, EE, 0);

    // ---- recurrence with PDL-chained launches ----
    for (int t = 0; t < TDEC; t++) {
        int cur = t & 1;
        const float* hcur = (const float*)(hbuf_dev + cur*BSZ*HH);
        launch_pdl(k_s1,  dim3(XX/8), dim3(256), hcur, bda, bfb);
        launch_pdl(k_s2a, dim3((PP + 7)/8, BSZ), dim3(256), Wfa, bfa);
        launch_pdl(k_s3f, dim3(DE/256, BSZ), dim3(256), t, feat, out_alpha);
        launch_pdl(k_s4f, dim3(HH/4), dim3(256), t, cur, Wih, bih, Whh, bhh);
    }

    // ---- epilogue: preds = Hall @ Wout + bout : M=640, N=30000, K=512 ----
    launch_pdl(k_gemm_tc, dim3((VV + 63)/64, (TDEC*BSZ)/128), dim3(256),
               (const float*)nullptr, 0, Wout, VV, bout,
               out_pred, VV, TDEC*BSZ, VV, HH, 2);
}

// round 10
// speedup vs baseline: 1.5239x; 1.0649x over previous
#include <cuda_runtime.h>
#include <math.h>

// ---- problem constants ----
#define BSZ   32
#define TT    22
#define PP    196
#define DE    2048
#define EE    512
#define HH    512
#define AA    512
#define VV    30000
#define TDEC  20
#define XX    2560   // E + DE
#define G4    2048   // 4*H
#define KAW   2048   // awe part of K in LSTM gemm
#define KS4   2560   // awe + h
#define NKS   4      // K-splits for gates GEMM
#define KTS   5      // K-tiles (of 128) per split: 4*5*128 = 2560

// ---- output layout ----
#define OFF_PRED  0
#define OFF_ALPHA (BSZ*TDEC*VV)
#define OFF_CAPS  (OFF_ALPHA + BSZ*TDEC*PP)
#define OFF_LEN   (OFF_CAPS + BSZ*TT)
#define OFF_SORT  (OFF_LEN + BSZ)

// ---- device scratch ----
__device__ float g_att1[BSZ*PP*AA];
__device__ float g_hbuf[2*BSZ*HH];
__device__ float g_c[BSZ*HH];
__device__ float g_att2[BSZ*AA];
__device__ float g_gateraw[BSZ*DE];
__device__ float g_escore[BSZ*PP];
__device__ float g_xawe[BSZ*KAW];
__device__ float g_Hall[TDEC*BSZ*HH];
__device__ float g_meanpart[4*BSZ*DE];
__device__ float g_embX[TDEC*BSZ*EE];
__device__ float g_WihET[EE*G4];
__device__ float g_pre[TDEC*BSZ*G4];
__device__ float g_WdaT[AA*HH];
__device__ float g_WfbT[DE*HH];
__device__ float g_Wh0T[HH*DE];
__device__ float g_Wc0T[HH*DE];
__device__ float g_part[NKS*128*16*BSZ];   // [ks][jb][v][b], 1 MB
__device__ int   g_sortind[BSZ];
__device__ int   g_declen[BSZ];
__device__ int   g_caps[BSZ*TT];
__device__ int   g_rowmapA[BSZ*PP];
__device__ int   g_rowmapC[BSZ*TDEC];
__device__ int   g_activeC[BSZ*TDEC];

__device__ __forceinline__ float sigm(float x) { return 1.0f / (1.0f + expf(-x)); }

__device__ __forceinline__ unsigned f2tf32(float f) {
    unsigned r;
    asm("cvt.rna.tf32.f32 %0, %1;" : "=r"(r) : "f"(f));
    return r;
}

__device__ __forceinline__ void mma_tf32(float* d, const uint4& a, const uint2& b) {
    asm("mma.sync.aligned.m16n8k8.row.col.f32.tf32.tf32.f32 "
        "{%0,%1,%2,%3},{%4,%5,%6,%7},{%8,%9},{%0,%1,%2,%3};"
        : "+f"(d[0]), "+f"(d[1]), "+f"(d[2]), "+f"(d[3])
        : "r"(a.x), "r"(a.y), "r"(a.z), "r"(a.w), "r"(b.x), "r"(b.y));
}

// ============================================================
// Setup
// ============================================================
__global__ void k_setup(const int* __restrict__ captions,
                        const int* __restrict__ cap_len,
                        float* __restrict__ out_caps,
                        float* __restrict__ out_len,
                        float* __restrict__ out_sort) {
    int tid = threadIdx.x;
    __shared__ int s_len[BSZ];
    __shared__ int s_sort[BSZ];
    __shared__ int s_dec[BSZ];
    if (tid < BSZ) s_len[tid] = cap_len[tid];
    __syncthreads();
    if (tid < BSZ) {
        int li = s_len[tid];
        int rank = 0;
        for (int j = 0; j < BSZ; j++) {
            int lj = s_len[j];
            if (lj > li || (lj == li && j < tid)) rank++;
        }
        s_sort[rank] = tid;
    }
    __syncthreads();
    if (tid < BSZ) {
        int src = s_sort[tid];
        g_sortind[tid] = src;
        int L = s_len[src];
        g_declen[tid] = L - 1;
        s_dec[tid]    = L - 1;
        out_len[tid]  = (float)L;
        out_sort[tid] = (float)src;
    }
    __syncthreads();
    for (int i = tid; i < BSZ*TT; i += blockDim.x) {
        int b = i / TT, t = i % TT;
        int v = captions[t*BSZ + s_sort[b]];
        g_caps[i] = v;
        out_caps[i] = (float)v;
    }
    for (int i = tid; i < BSZ*PP; i += blockDim.x) {
        int b = i / PP, p = i % PP;
        g_rowmapA[i] = s_sort[b]*PP + p;
    }
    for (int i = tid; i < BSZ*TDEC; i += blockDim.x) {
        int b = i / TDEC, t = i % TDEC;
        g_rowmapC[i] = t*BSZ + b;
        g_activeC[i] = (t < s_dec[b]) ? 1 : 0;
    }
}

// ============================================================
// Gather embeddings
// ============================================================
__global__ void k_embgather(const float* __restrict__ emb) {
    int t = blockIdx.x, b = blockIdx.y;
    int tok = g_caps[b*TT + t];
    const float* src = emb + (size_t)tok*EE;
    float* dst = g_embX + ((size_t)t*BSZ + b)*EE;
    for (int e = threadIdx.x; e < EE; e += blockDim.x) dst[e] = src[e];
}

// ============================================================
// Transpose
// ============================================================
__global__ void __launch_bounds__(256) k_trans(const float* __restrict__ src, int srcLd,
                                               float* __restrict__ dst, int dstLd) {
    __shared__ float ts[32][33];
    int r0 = blockIdx.x*32, c0 = blockIdx.y*32;
    int tx = threadIdx.x & 31, ty = threadIdx.x >> 5;
    #pragma unroll
    for (int rr = ty; rr < 32; rr += 8)
        ts[rr][tx] = src[(size_t)(r0 + rr)*srcLd + c0 + tx];
    __syncthreads();
    #pragma unroll
    for (int rr = ty; rr < 32; rr += 8)
        dst[(size_t)(c0 + rr)*dstLd + r0 + tx] = ts[tx][rr];
}

// ============================================================
// mean partials
// ============================================================
__global__ void k_meanpart(const float* __restrict__ feat) {
    int b = blockIdx.y, ps = blockIdx.z;
    int d = blockIdx.x*256 + threadIdx.x;
    const float* base = feat + (size_t)g_sortind[b]*PP*DE + d;
    float s = 0.f;
    int p0 = ps*49;
    #pragma unroll 7
    for (int p = p0; p < p0 + 49; p++) s += base[(size_t)p*DE];
    g_meanpart[((ps*BSZ) + b)*DE + d] = s;
}

// ============================================================
// h0/c0 (transposed weights)
// ============================================================
__global__ void __launch_bounds__(256) k_h0c0(const float* __restrict__ bh0,
                                              const float* __restrict__ bc0) {
    __shared__ float xs[BSZ][128];
    int tid = threadIdx.x, lane = tid & 31, w = tid >> 5;
    int c0 = blockIdx.x*8 + (w & 1)*4;
    int b0 = (w >> 1)*8;
    float acc[4][8];
    #pragma unroll
    for (int i = 0; i < 4; i++)
        #pragma unroll
        for (int jx = 0; jx < 8; jx++) acc[i][jx] = 0.f;

    for (int kt = 0; kt < DE/128; kt++) {
        #pragma unroll
        for (int s = 0; s < 16; s++) {
            int idx = tid + s*256;
            int bb = idx >> 7, kk = idx & 127;
            int gd = kt*128 + kk;
            float m = g_meanpart[(0*BSZ + bb)*DE + gd] + g_meanpart[(1*BSZ + bb)*DE + gd]
                    + g_meanpart[(2*BSZ + bb)*DE + gd] + g_meanpart[(3*BSZ + bb)*DE + gd];
            xs[bb][kk] = m * (1.0f/PP);
        }
        __syncthreads();
        #pragma unroll
        for (int kk4 = 0; kk4 < 4; kk4++) {
            int k = kt*128 + kk4*32 + lane;
            float wv[4];
            #pragma unroll
            for (int cc = 0; cc < 4; cc++) {
                int col = c0 + cc;
                wv[cc] = (col < HH) ? g_Wh0T[(size_t)col*DE + k] : g_Wc0T[(size_t)(col - HH)*DE + k];
            }
            #pragma unroll
            for (int cc = 0; cc < 4; cc++)
                #pragma unroll
                for (int bb = 0; bb < 8; bb++)
                    acc[cc][bb] = fmaf(wv[cc], xs[b0+bb][kk4*32+lane], acc[cc][bb]);
        }
        __syncthreads();
    }
    float out = 0.f;
    #pragma unroll
    for (int cc = 0; cc < 4; cc++)
        #pragma unroll
        for (int bb = 0; bb < 8; bb++) {
            float v = acc[cc][bb];
            #pragma unroll
            for (int off = 16; off; off >>= 1) v += __shfl_xor_sync(0xffffffffu, v, off);
            if (lane == cc*8 + bb) out = v;
        }
    int cc = lane >> 3, bb = lane & 7;
    int col = c0 + cc, b = b0 + bb;
    if (col < HH) g_hbuf[b*HH + col]   = out + bh0[col];
    else          g_c[b*HH + col - HH] = out + bc0[col - HH];
}

// ============================================================
// S1 (PDL): weights preamble, gridsync, GEMM; trigger AFTER stores.
// ============================================================
__global__ void __launch_bounds__(256) k_s1(const float* __restrict__ hcur,
                                            const float* __restrict__ bda,
                                            const float* __restrict__ bfb) {
    __shared__ float ws[8][HH];
    __shared__ float xs[BSZ][128];
    int tid = threadIdx.x, lane = tid & 31, w = tid >> 5;
    int cbase = blockIdx.x*8;

    {
        int cc = tid >> 5;
        int k0 = (tid & 31)*16;
        int col = cbase + cc;
        const float* src = (col < AA) ? (g_WdaT + (size_t)col*HH)
                                      : (g_WfbT + (size_t)(col - AA)*HH);
        #pragma unroll
        for (int q = 0; q < 4; q++)
            *(float4*)&ws[cc][k0 + q*4] = *(const float4*)(src + k0 + q*4);
    }

    cudaGridDependencySynchronize();

    int c0l = (w & 1)*4;
    int b0 = (w >> 1)*8;
    float acc[4][8];
    #pragma unroll
    for (int i = 0; i < 4; i++)
        #pragma unroll
        for (int jx = 0; jx < 8; jx++) acc[i][jx] = 0.f;

    #pragma unroll
    for (int kt = 0; kt < HH/128; kt++) {
        #pragma unroll
        for (int s = 0; s < 16; s++) {
            int idx = tid + s*256;
            int bb = idx >> 7, kk = idx & 127;
            xs[bb][kk] = hcur[bb*HH + kt*128 + kk];
        }
        __syncthreads();
        #pragma unroll
        for (int kk4 = 0; kk4 < 4; kk4++) {
            int k = kt*128 + kk4*32 + lane;
            float wv[4];
            #pragma unroll
            for (int cc = 0; cc < 4; cc++) wv[cc] = ws[c0l + cc][k];
            #pragma unroll
            for (int cc = 0; cc < 4; cc++)
                #pragma unroll
                for (int bb = 0; bb < 8; bb++)
                    acc[cc][bb] = fmaf(wv[cc], xs[b0+bb][kk4*32+lane], acc[cc][bb]);
        }
        __syncthreads();
    }
    float out = 0.f;
    #pragma unroll
    for (int cc = 0; cc < 4; cc++)
        #pragma unroll
        for (int bb = 0; bb < 8; bb++) {
            float v = acc[cc][bb];
            #pragma unroll
            for (int off = 16; off; off >>= 1) v += __shfl_xor_sync(0xffffffffu, v, off);
            if (lane == cc*8 + bb) out = v;
        }
    int cc = lane >> 3, bb = lane & 7;
    int col = cbase + c0l + cc, b = b0 + bb;
    if (col < AA) g_att2[b*AA + col]         = out + bda[col];
    else          g_gateraw[b*DE + col - AA] = out + bfb[col - AA];
    cudaTriggerProgrammaticLaunchCompletion();   // AFTER producing stores
}

// ============================================================
// S2a (PDL): att1+Wfa preamble, gridsync, att2; trigger AFTER store.
// ============================================================
__global__ void __launch_bounds__(256) k_s2a(const float* __restrict__ Wfa, const float* __restrict__ bfa) {
    int b = blockIdx.y;
    int tid = threadIdx.x, lane = tid & 31, w = tid >> 5;
    __shared__ float4 att2s4[AA/4], wfas4[AA/4];
    int p = blockIdx.x*8 + w;
    bool pvld = (p < PP);
    int psafe = pvld ? p : (PP - 1);

    float4 v[4];
    {
        const float4* row4 = (const float4*)(g_att1 + ((size_t)b*PP + psafe)*AA);
        #pragma unroll
        for (int c = 0; c < 4; c++) v[c] = row4[c*32 + lane];
        if (tid < AA/4) wfas4[tid] = ((const float4*)Wfa)[tid];
    }
    float bfa0 = bfa[0];

    cudaGridDependencySynchronize();

    if (tid < AA/4) att2s4[tid] = ((const float4*)(g_att2 + b*AA))[tid];
    __syncthreads();

    float acc = 0.f;
    #pragma unroll
    for (int c = 0; c < 4; c++) {
        int idx = c*32 + lane;
        float4 a2 = att2s4[idx];
        float4 wf = wfas4[idx];
        acc = fmaf(fmaxf(v[c].x + a2.x, 0.f), wf.x, acc);
        acc = fmaf(fmaxf(v[c].y + a2.y, 0.f), wf.y, acc);
        acc = fmaf(fmaxf(v[c].z + a2.z, 0.f), wf.z, acc);
        acc = fmaf(fmaxf(v[c].w + a2.w, 0.f), wf.w, acc);
    }
    #pragma unroll
    for (int off = 16; off; off >>= 1) acc += __shfl_xor_sync(0xffffffffu, acc, off);
    if (pvld && lane == 0) g_escore[b*PP + p] = acc + bfa0;
    cudaTriggerProgrammaticLaunchCompletion();   // AFTER producing store
}

// ============================================================
// S3f (PDL): softmax + awe + gate; trigger AFTER xawe store.
// ============================================================
__global__ void __launch_bounds__(256) k_s3f(int t, const float* __restrict__ feat,
                                             float* __restrict__ out_alphas) {
    int b = blockIdx.y, tid = threadIdx.x;
    __shared__ float als[PP];
    __shared__ float sred[256];

    cudaGridDependencySynchronize();

    float e = (tid < PP) ? g_escore[b*PP + tid] : -3.0e38f;
    sred[tid] = e;
    __syncthreads();
    for (int s = 128; s > 0; s >>= 1) { if (tid < s) sred[tid] = fmaxf(sred[tid], sred[tid+s]); __syncthreads(); }
    float mx = sred[0];
    __syncthreads();
    float ex = (tid < PP) ? expf(e - mx) : 0.f;
    sred[tid] = ex;
    __syncthreads();
    for (int s = 128; s > 0; s >>= 1) { if (tid < s) sred[tid] += sred[tid+s]; __syncthreads(); }
    float inv = 1.0f / sred[0];
    if (tid < PP) {
        float al = ex * inv;
        als[tid] = al;
        if (blockIdx.x == 0) {
            int active = (t < g_declen[b]);
            out_alphas[((size_t)b*TDEC + t)*PP + tid] = active ? al : 0.f;
        }
    }
    __syncthreads();

    int d = blockIdx.x*256 + tid;
    const float* base = feat + (size_t)g_sortind[b]*PP*DE + d;
    float s = 0.f;
    #pragma unroll 28
    for (int p = 0; p < PP; p++) s = fmaf(als[p], base[(size_t)p*DE], s);
    float gr = g_gateraw[b*DE + d];
    g_xawe[b*KAW + d] = sigm(gr) * s;
    cudaTriggerProgrammaticLaunchCompletion();   // AFTER producing store
}

// ============================================================
// S4p (PDL): split-K gates GEMM partials; trigger AFTER g_part.
// grid (128 jBlocks, 4 ksplits).
// ============================================================
__global__ void __launch_bounds__(256) k_s4p(int cur,
        const float* __restrict__ Wih, const float* __restrict__ Whh) {
    __shared__ float xs[BSZ][128];
    __shared__ float red[4][BSZ][33];
    __shared__ float gsum[16][BSZ];
    int tid = threadIdx.x, lane = tid & 31, w = tid >> 5;
    int jb = blockIdx.x;
    int ks = blockIdx.y;
    int jBlock = jb*4;
    int r0 = (w >> 1)*4;
    int bh = (w & 1)*16;
    const float* hcur = g_hbuf + cur*BSZ*HH;

    float acc[4][16];
    #pragma unroll
    for (int i = 0; i < 4; i++)
        #pragma unroll
        for (int jx = 0; jx < 16; jx++) acc[i][jx] = 0.f;

    const float* wrowIH[4];
    const float* wrowHH[4];
    #pragma unroll
    for (int cc = 0; cc < 4; cc++) {
        int v = r0 + cc;
        int wr = (v >> 2)*HH + jBlock + (v & 3);
        wrowIH[cc] = Wih + (size_t)wr*XX + EE;
        wrowHH[cc] = Whh + (size_t)wr*HH;
    }

    cudaGridDependencySynchronize();

    int kt0 = ks*KTS;
    float pv[16];
    #pragma unroll
    for (int s = 0; s < 16; s++) {
        int idx = tid + s*256;
        int bb = idx >> 7, kk = idx & 127;
        int gk = kt0*128 + kk;
        pv[s] = (gk < KAW) ? g_xawe[bb*KAW + gk] : hcur[bb*HH + gk - KAW];
    }
    #pragma unroll
    for (int s = 0; s < 16; s++) {
        int idx = tid + s*256;
        xs[idx >> 7][idx & 127] = pv[s];
    }
    __syncthreads();

    #pragma unroll
    for (int ki = 0; ki < KTS; ki++) {
        int kt = kt0 + ki;
        if (ki + 1 < KTS) {
            int gk0 = (kt + 1)*128;
            #pragma unroll
            for (int s = 0; s < 16; s++) {
                int idx = tid + s*256;
                int bb = idx >> 7, kk = idx & 127;
                int gk = gk0 + kk;
                pv[s] = (gk < KAW) ? g_xawe[bb*KAW + gk] : hcur[bb*HH + gk - KAW];
            }
        }
        #pragma unroll
        for (int kk4 = 0; kk4 < 4; kk4++) {
            int gk = kt*128 + kk4*32 + lane;
            float wv[4];
            #pragma unroll
            for (int cc = 0; cc < 4; cc++)
                wv[cc] = (gk < KAW) ? wrowIH[cc][gk] : wrowHH[cc][gk - KAW];
            #pragma unroll
            for (int bb = 0; bb < 16; bb++) {
                float xv = xs[bh + bb][kk4*32 + lane];
                #pragma unroll
                for (int cc = 0; cc < 4; cc++)
                    acc[cc][bb] = fmaf(wv[cc], xv, acc[cc][bb]);
            }
        }
        __syncthreads();
        if (ki + 1 < KTS) {
            #pragma unroll
            for (int s = 0; s < 16; s++) {
                int idx = tid + s*256;
                xs[idx >> 7][idx & 127] = pv[s];
            }
        }
        __syncthreads();
    }

    for (int rnd = 0; rnd < 4; rnd++) {
        if ((w >> 1) == rnd) {
            #pragma unroll
            for (int cc = 0; cc < 4; cc++)
                #pragma unroll
                for (int bb = 0; bb < 16; bb++)
                    red[cc][bh + bb][lane] = acc[cc][bb];
        }
        __syncthreads();
        if (tid < 128) {
            int cc = tid >> 5, b = tid & 31;
            float s = 0.f;
            #pragma unroll
            for (int l = 0; l < 32; l++) s += red[cc][b][l];
            gsum[rnd*4 + cc][b] = s;
        }
        __syncthreads();
    }

    // write partials: [ks][jb][v][b], b fastest -> coalesced
    #pragma unroll
    for (int i = tid; i < 512; i += 256) {
        int v = i >> 5, b = i & 31;
        g_part[(((size_t)ks*128 + jb)*16 + v)*BSZ + b] = gsum[v][b];
    }
    cudaTriggerProgrammaticLaunchCompletion();   // AFTER producing stores
}

// ============================================================
// S5 (PDL): reduce partials + bias + pre + LSTM cell.
// grid 128 (jb), block 512. Trigger AFTER h/c/Hall stores.
// ============================================================
__global__ void __launch_bounds__(512) k_s5(int t, int cur,
        const float* __restrict__ bih, const float* __restrict__ bhh) {
    __shared__ float gs[16][BSZ];
    int tid = threadIdx.x;
    int jb = blockIdx.x;
    const float* hcur = g_hbuf + cur*BSZ*HH;
    float*       hnxt = g_hbuf + (1 - cur)*BSZ*HH;

    cudaGridDependencySynchronize();

    {
        int v = tid >> 5, b = tid & 31;
        float s = 0.f;
        #pragma unroll
        for (int ks = 0; ks < NKS; ks++)
            s += g_part[(((size_t)ks*128 + jb)*16 + v)*BSZ + b];
        gs[v][b] = s;
    }
    __syncthreads();

    if (tid < 128) {
        int jj = tid >> 5, b = tid & 31;
        int j = jb*4 + jj;
        size_t pb = ((size_t)t*BSZ + b)*G4;
        float gi = gs[0*4 + jj][b] + bih[0*HH + j] + bhh[0*HH + j] + g_pre[pb + 0*HH + j];
        float gf = gs[1*4 + jj][b] + bih[1*HH + j] + bhh[1*HH + j] + g_pre[pb + 1*HH + j];
        float gg = gs[2*4 + jj][b] + bih[2*HH + j] + bhh[2*HH + j] + g_pre[pb + 2*HH + j];
        float go = gs[3*4 + jj][b] + bih[3*HH + j] + bhh[3*HH + j] + g_pre[pb + 3*HH + j];
        float c  = g_c[b*HH + j];
        float cn = sigm(gf)*c + sigm(gi)*tanhf(gg);
        float hn = sigm(go)*tanhf(cn);
        int active = (t < g_declen[b]);
        if (active) g_c[b*HH + j] = cn;
        hnxt[b*HH + j] = active ? hn : hcur[b*HH + j];
        g_Hall[((size_t)t*BSZ + b)*HH + j] = hn;
    }
    cudaTriggerProgrammaticLaunchCompletion();   // AFTER producing stores
}

// ============================================================
// TF32 tensor-core GEMM (mode 2 gains PDL gridsync before A).
// ============================================================
__global__ void __launch_bounds__(256) k_gemm_tc(const float* __restrict__ Aext, int lda_,
                                                 const float* __restrict__ Bext, int ldb_,
                                                 const float* __restrict__ biasext,
                                                 float* __restrict__ Cext, int ldc_,
                                                 int M, int N, int K, int mode) {
    __shared__ __align__(16) float Asm[2][32][128];
    __shared__ __align__(16) float Bsm[2][32][64];
    int tid = threadIdx.x;
    int lane = tid & 31, w = tid >> 5;
    int rowBase = blockIdx.y*128, colBase = blockIdx.x*64;

    const float* Ause; const float* Buse; const float* bias; float* Cuse;
    int lda, ldb, ldc;
    const int* rowmap = nullptr; const int* ract = nullptr;
    if (mode == 0)      { Ause = g_embX; lda = EE;   Buse = g_WihET; ldb = G4;   bias = nullptr; Cuse = g_pre;  ldc = G4; }
    else if (mode == 1) { Ause = Aext;   lda = lda_; Buse = Bext;    ldb = ldb_; bias = biasext; Cuse = g_att1; ldc = AA; rowmap = g_rowmapA; }
    else                { Ause = g_Hall; lda = HH;   Buse = Bext;    ldb = ldb_; bias = biasext; Cuse = Cext;   ldc = ldc_; rowmap = g_rowmapC; ract = g_activeC; }

    int wm = w >> 1;
    int wn = w & 1;

    int arow = tid >> 1;
    int acg  = (tid & 1) * 16;
    int a_mt   = arow >> 4;
    int a_rlow = arow & 15;
    int a_jlo  = a_rlow >> 3;
    int a_lb   = (a_rlow & 7) * 4;
    int gRow = rowBase + arow;
    int amap = rowmap ? rowmap[gRow] : gRow;
    const float* aptr = Ause + (size_t)amap*lda;

    int bk  = tid >> 3;
    int bm8 = tid & 7;
    int b_ks = bk >> 3;
    int b_kk = bk & 7;
    int b_jb = b_kk >> 2;
    int b_k3 = b_kk & 3;
    int bcol0 = colBase + bm8*8;

    float acc[2][4][4];
    #pragma unroll
    for (int mi = 0; mi < 2; mi++)
        #pragma unroll
        for (int ni = 0; ni < 4; ni++)
            #pragma unroll
            for (int e = 0; e < 4; e++) acc[mi][ni][e] = 0.f;

    float4 aR[4], bR[2];

    #pragma unroll
    for (int q = 0; q < 2; q++) {
        int c = bcol0 + q*4;
        bR[q] = (c < N) ? *(const float4*)(Buse + (size_t)bk*ldb + c)
                        : make_float4(0.f,0.f,0.f,0.f);
    }
    if (mode == 2) cudaGridDependencySynchronize();
    #pragma unroll
    for (int q = 0; q < 4; q++) aR[q] = *(const float4*)(aptr + acg + q*4);
    {
        #pragma unroll
        for (int q = 0; q < 4; q++) {
            int kc = acg + q*4;
            int ks = kc >> 3;
            int jhi = (kc & 4) ? 2 : 0;
            float* tb = &Asm[0][a_mt*4 + ks][0];
            int j = a_jlo + jhi;
            int c0 = a_lb + 0, c1 = a_lb + 1, c2 = a_lb + 2, c3 = a_lb + 3;
            tb[(c0 ^ (c0 >> 3))*4 + j] = __uint_as_float(f2tf32(aR[q].x));
            tb[(c1 ^ (c1 >> 3))*4 + j] = __uint_as_float(f2tf32(aR[q].y));
            tb[(c2 ^ (c2 >> 3))*4 + j] = __uint_as_float(f2tf32(aR[q].z));
            tb[(c3 ^ (c3 >> 3))*4 + j] = __uint_as_float(f2tf32(aR[q].w));
        }
        #pragma unroll
        for (int q = 0; q < 2; q++) {
            float* tb = &Bsm[0][bm8*4 + b_ks][0];
            int rot = bm8*4;
            #pragma unroll
            for (int e = 0; e < 4; e++) {
                int cc = q*4 + e;
                int ch = ((cc*4 + b_k3) + rot) & 31;
                float v = (e == 0) ? bR[q].x : (e == 1) ? bR[q].y : (e == 2) ? bR[q].z : bR[q].w;
                tb[ch*2 + b_jb] = __uint_as_float(f2tf32(v));
            }
        }
    }
    __syncthreads();

    int nch = K / 32;
    for (int ch = 0; ch < nch; ch++) {
        int buf = ch & 1;
        if (ch + 1 < nch) {
            int k0 = (ch + 1)*32;
            #pragma unroll
            for (int q = 0; q < 4; q++) aR[q] = *(const float4*)(aptr + k0 + acg + q*4);
            #pragma unroll
            for (int q = 0; q < 2; q++) {
                int c = bcol0 + q*4;
                bR[q] = (c < N) ? *(const float4*)(Buse + (size_t)(k0 + bk)*ldb + c)
                                : make_float4(0.f,0.f,0.f,0.f);
            }
        }
        int aswl = (lane ^ (lane >> 3)) * 4;
        #pragma unroll
        for (int ks = 0; ks < 4; ks++) {
            uint4 af[2]; uint2 bf[4];
            #pragma unroll
            for (int mi = 0; mi < 2; mi++)
                af[mi] = *(const uint4*)&Asm[buf][(wm*2 + mi)*4 + ks][aswl];
            #pragma unroll
            for (int ni = 0; ni < 4; ni++) {
                int nt = wn*4 + ni;
                int chn = (lane + nt*4) & 31;
                bf[ni] = *(const uint2*)&Bsm[buf][nt*4 + ks][chn*2];
            }
            #pragma unroll
            for (int mi = 0; mi < 2; mi++)
                #pragma unroll
                for (int ni = 0; ni < 4; ni++)
                    mma_tf32(acc[mi][ni], af[mi], bf[ni]);
        }
        if (ch + 1 < nch) {
            int nb = buf ^ 1;
            #pragma unroll
            for (int q = 0; q < 4; q++) {
                int kc = acg + q*4;
                int ks = kc >> 3;
                int jhi = (kc & 4) ? 2 : 0;
                float* tb = &Asm[nb][a_mt*4 + ks][0];
                int j = a_jlo + jhi;
                int c0 = a_lb + 0, c1 = a_lb + 1, c2 = a_lb + 2, c3 = a_lb + 3;
                tb[(c0 ^ (c0 >> 3))*4 + j] = __uint_as_float(f2tf32(aR[q].x));
                tb[(c1 ^ (c1 >> 3))*4 + j] = __uint_as_float(f2tf32(aR[q].y));
                tb[(c2 ^ (c2 >> 3))*4 + j] = __uint_as_float(f2tf32(aR[q].z));
                tb[(c3 ^ (c3 >> 3))*4 + j] = __uint_as_float(f2tf32(aR[q].w));
            }
            #pragma unroll
            for (int q = 0; q < 2; q++) {
                float* tb = &Bsm[nb][bm8*4 + b_ks][0];
                int rot = bm8*4;
                #pragma unroll
                for (int e = 0; e < 4; e++) {
                    int cc = q*4 + e;
                    int ch2 = ((cc*4 + b_k3) + rot) & 31;
                    float v = (e == 0) ? bR[q].x : (e == 1) ? bR[q].y : (e == 2) ? bR[q].z : bR[q].w;
                    tb[ch2*2 + b_jb] = __uint_as_float(f2tf32(v));
                }
            }
            __syncthreads();
        }
    }

    #pragma unroll
    for (int mi = 0; mi < 2; mi++) {
        int r0 = rowBase + wm*32 + mi*16 + (lane >> 2);
        int r1 = r0 + 8;
        int act0 = ract ? ract[r0] : 1;
        int act1 = ract ? ract[r1] : 1;
        #pragma unroll
        for (int ni = 0; ni < 4; ni++) {
            int col = colBase + wn*32 + ni*8 + (lane & 3)*2;
            if (col < N) {
                float b0v = bias ? bias[col]     : 0.f;
                float b1v = bias ? bias[col + 1] : 0.f;
                float2 v0, v1;
                v0.x = act0 ? (acc[mi][ni][0] + b0v) : 0.f;
                v0.y = act0 ? (acc[mi][ni][1] + b1v) : 0.f;
                v1.x = act1 ? (acc[mi][ni][2] + b0v) : 0.f;
                v1.y = act1 ? (acc[mi][ni][3] + b1v) : 0.f;
                *(float2*)&Cuse[(size_t)r0*ldc + col] = v0;
                *(float2*)&Cuse[(size_t)r1*ldc + col] = v1;
            }
        }
    }
}

// ============================================================
// host-side PDL launch helper
// ============================================================
template <typename F, typename... Args>
static inline void launch_pdl(F kernel, dim3 grid, dim3 block, Args... args) {
    cudaLaunchConfig_t cfg = {};
    cfg.gridDim = grid;
    cfg.blockDim = block;
    cudaLaunchAttribute attr[1];
    attr[0].id = cudaLaunchAttributeProgrammaticStreamSerialization;
    attr[0].val.programmaticStreamSerializationAllowed = 1;
    cfg.attrs = attr;
    cfg.numAttrs = 1;
    cudaLaunchKernelEx(&cfg, kernel, args...);
}

// ============================================================
extern "C" void kernel_launch(void* const* d_in, const int* in_sizes, int n_in,
                              void* d_out, int out_size) {
    const float* feat     = (const float*)d_in[0];
    const int*   captions = (const int*)  d_in[1];
    const int*   caplen   = (const int*)  d_in[2];
    const float* emb      = (const float*)d_in[3];
    const float* Wea = (const float*)d_in[4];  const float* bea = (const float*)d_in[5];
    const float* Wda = (const float*)d_in[6];  const float* bda = (const float*)d_in[7];
    const float* Wfa = (const float*)d_in[8];  const float* bfa = (const float*)d_in[9];
    const float* Wih = (const float*)d_in[10]; const float* bih = (const float*)d_in[11];
    const float* Whh = (const float*)d_in[12]; const float* bhh = (const float*)d_in[13];
    const float* Wh0 = (const float*)d_in[14]; const float* bh0 = (const float*)d_in[15];
    const float* Wc0 = (const float*)d_in[16]; const float* bc0 = (const float*)d_in[17];
    const float* Wfb = (const float*)d_in[18]; const float* bfb = (const float*)d_in[19];
    const float* Wout = (const float*)d_in[20]; const float* bout = (const float*)d_in[21];

    float* out = (float*)d_out;
    float* out_pred  = out + OFF_PRED;
    float* out_alpha = out + OFF_ALPHA;
    float* out_caps  = out + OFF_CAPS;
    float* out_len   = out + OFF_LEN;
    float* out_sort  = out + OFF_SORT;

    float* hbuf_dev = nullptr;  cudaGetSymbolAddress((void**)&hbuf_dev, g_hbuf);
    float* WihET_dev = nullptr; cudaGetSymbolAddress((void**)&WihET_dev, g_WihET);
    float* WdaT_dev = nullptr;  cudaGetSymbolAddress((void**)&WdaT_dev, g_WdaT);
    float* WfbT_dev = nullptr;  cudaGetSymbolAddress((void**)&WfbT_dev, g_WfbT);
    float* Wh0T_dev = nullptr;  cudaGetSymbolAddress((void**)&Wh0T_dev, g_Wh0T);
    float* Wc0T_dev = nullptr;  cudaGetSymbolAddress((void**)&Wc0T_dev, g_Wc0T);

    // ---- prologue: launches #4 AND #6 are k_gemm_tc (ncu targets) ----
    k_setup<<<1, 256>>>(captions, caplen, out_caps, out_len, out_sort);          // 1
    k_embgather<<<dim3(TDEC, BSZ), 128>>>(emb);                                  // 2
    k_trans<<<dim3(2048/32, 512/32), 256>>>(Wih, XX, WihET_dev, G4);             // 3
    // att1 = enc @ Wea + bea : M=6272, N=512, K=2048
    k_gemm_tc<<<dim3(AA/64, (BSZ*PP)/128), 256>>>(feat, DE, Wea, AA, bea,        // 4
                                                  nullptr, 0, BSZ*PP, AA, DE, 1);
    k_trans<<<dim3(512/32, 512/32),  256>>>(Wda, AA, WdaT_dev, HH);              // 5
    // pre = embX @ WihET : M=640, N=2048, K=512
    k_gemm_tc<<<dim3(G4/64, (TDEC*BSZ)/128), 256>>>(nullptr, 0, nullptr, 0, nullptr,   // 6
                                                    nullptr, 0, TDEC*BSZ, G4, EE, 0);
    k_trans<<<dim3(512/32, 2048/32), 256>>>(Wfb, DE, WfbT_dev, HH);              // 7
    k_trans<<<dim3(2048/32, 512/32), 256>>>(Wh0, HH, Wh0T_dev, DE);              // 8
    k_trans<<<dim3(2048/32, 512/32), 256>>>(Wc0, HH, Wc0T_dev, DE);              // 9
    k_meanpart<<<dim3(DE/256, BSZ, 4), 256>>>(feat);                             // 10
    k_h0c0<<<128, 256>>>(bh0, bc0);                                              // 11

    // ---- recurrence with PDL-chained launches ----
    for (int t = 0; t < TDEC; t++) {
        int cur = t & 1;
        const float* hcur = (const float*)(hbuf_dev + cur*BSZ*HH);
        launch_pdl(k_s1,  dim3(XX/8), dim3(256), hcur, bda, bfb);
        launch_pdl(k_s2a, dim3((PP + 7)/8, BSZ), dim3(256), Wfa, bfa);
        launch_pdl(k_s3f, dim3(DE/256, BSZ), dim3(256), t, feat, out_alpha);
        launch_pdl(k_s4p, dim3(128, NKS), dim3(256), cur, Wih, Whh);
        launch_pdl(k_s5,  dim3(128), dim3(512), t, cur, bih, bhh);
    }

    // ---- epilogue: preds = Hall @ Wout + bout : M=640, N=30000, K=512 ----
    launch_pdl(k_gemm_tc, dim3((VV + 63)/64, (TDEC*BSZ)/128), dim3(256),
               (const float*)nullptr, 0, Wout, VV, bout,
               out_pred, VV, TDEC*BSZ, VV, HH, 2);
}